// round 1
// baseline (speedup 1.0000x reference)
#include <cuda_runtime.h>
#include <math.h>

#define D 128
#define EPS 1e-5f
#define PADX 132
#define NODE_CAP 20096
#define E_MAX 640000

static const int SMEM_BYTES = (128 * PADX + 128 * 128) * 4;  // 133120 B

// ---------------- scratch (static device allocations are allowed) ----------
__device__ float g_t1[(size_t)E_MAX * D];     // edge MLP0 pre-BN output
__device__ float g_u [(size_t)E_MAX * D];     // edge MLP1 pre-BN output
__device__ float g_v [(size_t)NODE_CAP * D];  // node MLP2 pre-BN output
__device__ float g_w [(size_t)NODE_CAP * D];  // node MLP3 pre-BN output
__device__ float g_P1[(size_t)NODE_CAP * D];  // hn @ eW1[128:256]
__device__ float g_P2[(size_t)NODE_CAP * D];  // hn @ eW1[256:384]
__device__ float g_agg[(size_t)NODE_CAP * D];
__device__ float g_deg[NODE_CAP];
__device__ float g_stats[5 * 2 * 128];        // per stage: colsum[128], colsumsq[128]
__device__ float g_bnA[5 * 128];              // folded BN scale
__device__ float g_bnC[5 * 128];              // folded BN shift

// ---------------- helpers --------------------------------------------------
__device__ __forceinline__ float elu1(float x) { return x > 0.f ? x : expm1f(x); }

// packed fp32x2 FMA (sm_100+): 2x fp32 throughput vs 3-reg FFMA
__device__ __forceinline__ float2 ffma2(float2 d, float2 a, float2 b) {
    asm("fma.rn.f32x2 %0, %1, %2, %0;"
        : "+l"(reinterpret_cast<unsigned long long &>(d))
        : "l"(reinterpret_cast<unsigned long long &>(a)),
          "l"(reinterpret_cast<unsigned long long &>(b)));
    return d;
}

// C[128x128] += Xs[128x128] @ Ws[128x128]; thread (tx,ty) owns rows ty+16j, cols tx+16i
__device__ __forceinline__ void gemm_tile(const float* __restrict__ Xs,
                                          const float* __restrict__ Ws,
                                          float2 acc[8][4], int tx, int ty) {
#pragma unroll 2
    for (int k = 0; k < 128; k++) {
        float xv[8];
        float2 ww[4];
#pragma unroll
        for (int j = 0; j < 8; j++) xv[j] = Xs[(ty + 16 * j) * PADX + k];
#pragma unroll
        for (int p = 0; p < 4; p++) {
            float w0 = Ws[k * 128 + tx + 32 * p];
            float w1 = Ws[k * 128 + tx + 32 * p + 16];
            ww[p] = make_float2(w0, w1);
        }
#pragma unroll
        for (int j = 0; j < 8; j++) {
            float2 xx = make_float2(xv[j], xv[j]);
#pragma unroll
            for (int p = 0; p < 4; p++) acc[j][p] = ffma2(acc[j][p], xx, ww[p]);
        }
    }
}

// ---------------- fused MLP (GEMM-ELU-GEMM-ELU + column stats) -------------
// mode 0: X raw    mode 1: X*preA+preC (folded BN)    mode 2: X / max(deg,1)
__global__ void __launch_bounds__(256, 1)
mlp_kernel(const float* __restrict__ X,
           const float* __restrict__ W1, const float* __restrict__ B1,
           const float* __restrict__ W2, const float* __restrict__ B2,
           float* __restrict__ out, int nrows, int mode, int stage,
           const float* __restrict__ preA, const float* __restrict__ preC,
           const float* __restrict__ degp)
{
    extern __shared__ float smem[];
    float* Xs = smem;                  // 128 x PADX
    float* Ws = smem + 128 * PADX;     // 128 x 128
    __shared__ float sB[128];
    __shared__ float sPA[128], sPC[128], sDeg[128];

    const int tid = threadIdx.x;
    const int tx = tid & 15, ty = tid >> 4;
    const int row0 = blockIdx.x * 128;

    if (tid < 128) {
        sB[tid] = B1[tid];
        if (mode == 1) { sPA[tid] = preA[tid]; sPC[tid] = preC[tid]; }
        if (mode == 2) {
            int r = row0 + tid;
            sDeg[tid] = (r < nrows) ? (1.f / fmaxf(degp[r], 1.f)) : 0.f;
        }
    }
    __syncthreads();

#pragma unroll
    for (int t = 0; t < 16; t++) {
        int idx = tid + t * 256;
        int r = idx >> 5;
        int c4 = (idx & 31) << 2;
        int gr = row0 + r;
        float4 v = make_float4(0.f, 0.f, 0.f, 0.f);
        if (gr < nrows) {
            v = *reinterpret_cast<const float4*>(X + (size_t)gr * D + c4);
            if (mode == 1) {
                v.x = v.x * sPA[c4] + sPC[c4];
                v.y = v.y * sPA[c4 + 1] + sPC[c4 + 1];
                v.z = v.z * sPA[c4 + 2] + sPC[c4 + 2];
                v.w = v.w * sPA[c4 + 3] + sPC[c4 + 3];
            } else if (mode == 2) {
                float s = sDeg[r];
                v.x *= s; v.y *= s; v.z *= s; v.w *= s;
            }
        }
        *reinterpret_cast<float4*>(Xs + r * PADX + c4) = v;
        reinterpret_cast<float4*>(Ws)[idx] = reinterpret_cast<const float4*>(W1)[idx];
    }
    __syncthreads();

    float2 acc[8][4];
#pragma unroll
    for (int j = 0; j < 8; j++)
#pragma unroll
        for (int p = 0; p < 4; p++)
            acc[j][p] = make_float2(sB[tx + 32 * p], sB[tx + 32 * p + 16]);

    gemm_tile(Xs, Ws, acc, tx, ty);
#pragma unroll
    for (int j = 0; j < 8; j++)
#pragma unroll
        for (int p = 0; p < 4; p++) {
            acc[j][p].x = elu1(acc[j][p].x);
            acc[j][p].y = elu1(acc[j][p].y);
        }
    __syncthreads();  // all GEMM1 reads of Xs/Ws done

    // stash h1 into Xs, load W2/b2
#pragma unroll
    for (int j = 0; j < 8; j++) {
        int r = ty + 16 * j;
#pragma unroll
        for (int p = 0; p < 4; p++) {
            Xs[r * PADX + tx + 32 * p]      = acc[j][p].x;
            Xs[r * PADX + tx + 32 * p + 16] = acc[j][p].y;
        }
    }
#pragma unroll
    for (int t = 0; t < 16; t++) {
        int idx = tid + t * 256;
        reinterpret_cast<float4*>(Ws)[idx] = reinterpret_cast<const float4*>(W2)[idx];
    }
    if (tid < 128) sB[tid] = B2[tid];
    __syncthreads();

#pragma unroll
    for (int j = 0; j < 8; j++)
#pragma unroll
        for (int p = 0; p < 4; p++)
            acc[j][p] = make_float2(sB[tx + 32 * p], sB[tx + 32 * p + 16]);

    gemm_tile(Xs, Ws, acc, tx, ty);
#pragma unroll
    for (int j = 0; j < 8; j++)
#pragma unroll
        for (int p = 0; p < 4; p++) {
            acc[j][p].x = elu1(acc[j][p].x);
            acc[j][p].y = elu1(acc[j][p].y);
        }
    __syncthreads();  // GEMM2 reads of Xs done; Xs reused as Cs

#pragma unroll
    for (int j = 0; j < 8; j++) {
        int r = ty + 16 * j;
        int gr = row0 + r;
        bool valid = gr < nrows;
#pragma unroll
        for (int p = 0; p < 4; p++) {
            int c0 = tx + 32 * p, c1 = c0 + 16;
            float vx = valid ? acc[j][p].x : 0.f;
            float vy = valid ? acc[j][p].y : 0.f;
            Xs[r * PADX + c0] = vx;
            Xs[r * PADX + c1] = vy;
            if (valid) {
                out[(size_t)gr * D + c0] = vx;
                out[(size_t)gr * D + c1] = vy;
            }
        }
    }
    __syncthreads();

    if (tid < 128) {
        float s = 0.f, q = 0.f;
#pragma unroll 4
        for (int r = 0; r < 128; r++) {
            float vv = Xs[r * PADX + tid];
            s += vv; q += vv * vv;
        }
        atomicAdd(&g_stats[stage * 256 + tid], s);
        atomicAdd(&g_stats[stage * 256 + 128 + tid], q);
    }
}

// ---------------- BN finalize: fold into per-column affine -----------------
__global__ void finalize_bn(int stage, float cnt,
                            const float* __restrict__ g, const float* __restrict__ bt)
{
    int j = threadIdx.x;
    float s1 = g_stats[stage * 256 + j];
    float s2 = g_stats[stage * 256 + 128 + j];
    float mu = s1 / cnt;
    float var = s2 / cnt - mu * mu;
    float a = g[j] * rsqrtf(var + EPS);
    g_bnA[stage * 128 + j] = a;
    g_bnC[stage * 128 + j] = bt[j] - mu * a;
}

// ---------------- h_e = BN0(t1) + BN1(u); scatter-mean numerators ----------
__global__ void __launch_bounds__(256)
scatter_kernel(const int* __restrict__ dst, int nedges)
{
    int lane = threadIdx.x & 31;
    int warp = (blockIdx.x * 256 + threadIdx.x) >> 5;
    int nw = (gridDim.x * 256) >> 5;
    float4 A0 = reinterpret_cast<const float4*>(g_bnA)[lane];
    float4 C0 = reinterpret_cast<const float4*>(g_bnC)[lane];
    float4 A1 = reinterpret_cast<const float4*>(g_bnA + 128)[lane];
    float4 C1 = reinterpret_cast<const float4*>(g_bnC + 128)[lane];
    for (int e = warp; e < nedges; e += nw) {
        int d = __ldg(dst + e);
        float4 t = reinterpret_cast<const float4*>(g_t1 + (size_t)e * D)[lane];
        float4 u = reinterpret_cast<const float4*>(g_u + (size_t)e * D)[lane];
        float4 h;
        h.x = (t.x * A0.x + C0.x) + (u.x * A1.x + C1.x);
        h.y = (t.y * A0.y + C0.y) + (u.y * A1.y + C1.y);
        h.z = (t.z * A0.z + C0.z) + (u.z * A1.z + C1.z);
        h.w = (t.w * A0.w + C0.w) + (u.w * A1.w + C1.w);
        float* base = g_agg + (size_t)d * D + lane * 4;
        atomicAdd(base + 0, h.x);
        atomicAdd(base + 1, h.y);
        atomicAdd(base + 2, h.z);
        atomicAdd(base + 3, h.w);
        if (lane == 0) atomicAdd(&g_deg[d], 1.f);
    }
}

// -------- h_n = BN3(w)+BN2(v); P1 = h_n@eW1[128:256]; P2 = h_n@eW1[256:384]
__global__ void __launch_bounds__(256, 1)
node_final_kernel(const float* __restrict__ eW1, int nrows)
{
    extern __shared__ float smem[];
    float* Hs = smem;
    float* Ws = smem + 128 * PADX;
    const int tid = threadIdx.x;
    const int tx = tid & 15, ty = tid >> 4;
    const int row0 = blockIdx.x * 128;

#pragma unroll
    for (int t = 0; t < 16; t++) {
        int idx = tid + t * 256;
        int r = idx >> 5;
        int c4 = (idx & 31) << 2;
        int gr = row0 + r;
        float4 h = make_float4(0.f, 0.f, 0.f, 0.f);
        if (gr < nrows) {
            float4 v = *reinterpret_cast<const float4*>(g_v + (size_t)gr * D + c4);
            float4 w = *reinterpret_cast<const float4*>(g_w + (size_t)gr * D + c4);
            float4 A2 = reinterpret_cast<const float4*>(g_bnA + 256)[c4 >> 2];
            float4 C2 = reinterpret_cast<const float4*>(g_bnC + 256)[c4 >> 2];
            float4 A3 = reinterpret_cast<const float4*>(g_bnA + 384)[c4 >> 2];
            float4 C3 = reinterpret_cast<const float4*>(g_bnC + 384)[c4 >> 2];
            h.x = (w.x * A3.x + C3.x) + (v.x * A2.x + C2.x);
            h.y = (w.y * A3.y + C3.y) + (v.y * A2.y + C2.y);
            h.z = (w.z * A3.z + C3.z) + (v.z * A2.z + C2.z);
            h.w = (w.w * A3.w + C3.w) + (v.w * A2.w + C2.w);
        }
        *reinterpret_cast<float4*>(Hs + r * PADX + c4) = h;
        reinterpret_cast<float4*>(Ws)[idx] =
            reinterpret_cast<const float4*>(eW1 + 128 * 128)[idx];
    }
    __syncthreads();

    float2 acc[8][4];
#pragma unroll
    for (int j = 0; j < 8; j++)
#pragma unroll
        for (int p = 0; p < 4; p++) acc[j][p] = make_float2(0.f, 0.f);
    gemm_tile(Hs, Ws, acc, tx, ty);
    __syncthreads();

#pragma unroll
    for (int j = 0; j < 8; j++) {
        int gr = row0 + ty + 16 * j;
        if (gr < nrows)
#pragma unroll
            for (int p = 0; p < 4; p++) {
                g_P1[(size_t)gr * D + tx + 32 * p]      = acc[j][p].x;
                g_P1[(size_t)gr * D + tx + 32 * p + 16] = acc[j][p].y;
            }
    }
#pragma unroll
    for (int t = 0; t < 16; t++) {
        int idx = tid + t * 256;
        reinterpret_cast<float4*>(Ws)[idx] =
            reinterpret_cast<const float4*>(eW1 + 256 * 128)[idx];
    }
    __syncthreads();

#pragma unroll
    for (int j = 0; j < 8; j++)
#pragma unroll
        for (int p = 0; p < 4; p++) acc[j][p] = make_float2(0.f, 0.f);
    gemm_tile(Hs, Ws, acc, tx, ty);

#pragma unroll
    for (int j = 0; j < 8; j++) {
        int gr = row0 + ty + 16 * j;
        if (gr < nrows)
#pragma unroll
            for (int p = 0; p < 4; p++) {
                g_P2[(size_t)gr * D + tx + 32 * p]      = acc[j][p].x;
                g_P2[(size_t)gr * D + tx + 32 * p + 16] = acc[j][p].y;
            }
    }
}

// -------- final edge MLP: ELU(edata@eW1a + P1[src] + P2[dst] + eb1)@eW2 ...
__global__ void __launch_bounds__(256, 1)
final_edge_kernel(const float* __restrict__ edata,
                  const int* __restrict__ src, const int* __restrict__ dst,
                  const float* __restrict__ eW1, const float* __restrict__ eb1,
                  const float* __restrict__ eW2, const float* __restrict__ eb2,
                  float* __restrict__ out, int nrows)
{
    extern __shared__ float smem[];
    float* Xs = smem;
    float* Ws = smem + 128 * PADX;
    __shared__ int sSrc[128], sDst[128];
    __shared__ float sB[128];

    const int tid = threadIdx.x;
    const int tx = tid & 15, ty = tid >> 4;
    const int row0 = blockIdx.x * 128;

    if (tid < 128) {
        int gr = row0 + tid;
        sSrc[tid] = (gr < nrows) ? src[gr] : 0;
        sDst[tid] = (gr < nrows) ? dst[gr] : 0;
        sB[tid] = eb1[tid];
    }
#pragma unroll
    for (int t = 0; t < 16; t++) {
        int idx = tid + t * 256;
        int r = idx >> 5;
        int c4 = (idx & 31) << 2;
        int gr = row0 + r;
        float4 v = make_float4(0.f, 0.f, 0.f, 0.f);
        if (gr < nrows) v = *reinterpret_cast<const float4*>(edata + (size_t)gr * D + c4);
        *reinterpret_cast<float4*>(Xs + r * PADX + c4) = v;
        reinterpret_cast<float4*>(Ws)[idx] = reinterpret_cast<const float4*>(eW1)[idx];
    }
    __syncthreads();

    float2 acc[8][4];
#pragma unroll
    for (int j = 0; j < 8; j++)
#pragma unroll
        for (int p = 0; p < 4; p++)
            acc[j][p] = make_float2(sB[tx + 32 * p], sB[tx + 32 * p + 16]);
    gemm_tile(Xs, Ws, acc, tx, ty);

    // add node contributions (L2-resident gathers) + ELU
#pragma unroll
    for (int j = 0; j < 8; j++) {
        int r = ty + 16 * j;
        const float* p1 = g_P1 + (size_t)sSrc[r] * D;
        const float* p2 = g_P2 + (size_t)sDst[r] * D;
#pragma unroll
        for (int p = 0; p < 4; p++) {
            int c0 = tx + 32 * p, c1 = c0 + 16;
            acc[j][p].x = elu1(acc[j][p].x + p1[c0] + p2[c0]);
            acc[j][p].y = elu1(acc[j][p].y + p1[c1] + p2[c1]);
        }
    }
    __syncthreads();

#pragma unroll
    for (int j = 0; j < 8; j++) {
        int r = ty + 16 * j;
#pragma unroll
        for (int p = 0; p < 4; p++) {
            Xs[r * PADX + tx + 32 * p]      = acc[j][p].x;
            Xs[r * PADX + tx + 32 * p + 16] = acc[j][p].y;
        }
    }
#pragma unroll
    for (int t = 0; t < 16; t++) {
        int idx = tid + t * 256;
        reinterpret_cast<float4*>(Ws)[idx] = reinterpret_cast<const float4*>(eW2)[idx];
    }
    if (tid < 128) sB[tid] = eb2[tid];
    __syncthreads();

#pragma unroll
    for (int j = 0; j < 8; j++)
#pragma unroll
        for (int p = 0; p < 4; p++)
            acc[j][p] = make_float2(sB[tx + 32 * p], sB[tx + 32 * p + 16]);
    gemm_tile(Xs, Ws, acc, tx, ty);
#pragma unroll
    for (int j = 0; j < 8; j++)
#pragma unroll
        for (int p = 0; p < 4; p++) {
            acc[j][p].x = elu1(acc[j][p].x);
            acc[j][p].y = elu1(acc[j][p].y);
        }
    __syncthreads();

#pragma unroll
    for (int j = 0; j < 8; j++) {
        int r = ty + 16 * j;
        int gr = row0 + r;
        bool valid = gr < nrows;
#pragma unroll
        for (int p = 0; p < 4; p++) {
            int c0 = tx + 32 * p, c1 = c0 + 16;
            float vx = valid ? acc[j][p].x : 0.f;
            float vy = valid ? acc[j][p].y : 0.f;
            Xs[r * PADX + c0] = vx;
            Xs[r * PADX + c1] = vy;
            if (valid) {
                out[(size_t)gr * D + c0] = vx;
                out[(size_t)gr * D + c1] = vy;
            }
        }
    }
    __syncthreads();

    if (tid < 128) {
        float s = 0.f, q = 0.f;
#pragma unroll 4
        for (int r = 0; r < 128; r++) {
            float vv = Xs[r * PADX + tid];
            s += vv; q += vv * vv;
        }
        atomicAdd(&g_stats[4 * 256 + tid], s);
        atomicAdd(&g_stats[4 * 256 + 128 + tid], q);
    }
}

// ---------------- final in-place BN on the output --------------------------
__global__ void norm_out_kernel(float* __restrict__ out, int n4)
{
    int idx = blockIdx.x * blockDim.x + threadIdx.x;
    if (idx >= n4) return;
    int cv = idx & 31;
    float4 A = reinterpret_cast<const float4*>(g_bnA + 512)[cv];
    float4 C = reinterpret_cast<const float4*>(g_bnC + 512)[cv];
    float4 v = reinterpret_cast<float4*>(out)[idx];
    v.x = v.x * A.x + C.x;
    v.y = v.y * A.y + C.y;
    v.z = v.z * A.z + C.z;
    v.w = v.w * A.w + C.w;
    reinterpret_cast<float4*>(out)[idx] = v;
}

// ---------------- host orchestration --------------------------------------
extern "C" void kernel_launch(void* const* d_in, const int* in_sizes, int n_in,
                              void* d_out, int out_size)
{
    if (n_in < 15) return;
    const float* edata = (const float*)d_in[0];
    const int*   src   = (const int*)d_in[1];
    const int*   dst   = (const int*)d_in[2];
    int w = (n_in >= 16) ? 4 : 3;  // n_nodes scalar may or may not be passed
    const float* W1s = (const float*)d_in[w + 0];
    const float* b1s = (const float*)d_in[w + 1];
    const float* W2s = (const float*)d_in[w + 2];
    const float* b2s = (const float*)d_in[w + 3];
    const float* gs  = (const float*)d_in[w + 4];
    const float* bts = (const float*)d_in[w + 5];
    const float* eW1 = (const float*)d_in[w + 6];
    const float* eb1 = (const float*)d_in[w + 7];
    const float* eW2 = (const float*)d_in[w + 8];
    const float* eb2 = (const float*)d_in[w + 9];
    const float* eg  = (const float*)d_in[w + 10];
    const float* ebt = (const float*)d_in[w + 11];

    int E = in_sizes[0] / D;
    int N = 20000;

    float *p_t1, *p_u, *p_v, *p_w2, *p_agg, *p_deg, *p_stats, *p_bnA, *p_bnC;
    cudaGetSymbolAddress((void**)&p_t1, g_t1);
    cudaGetSymbolAddress((void**)&p_u, g_u);
    cudaGetSymbolAddress((void**)&p_v, g_v);
    cudaGetSymbolAddress((void**)&p_w2, g_w);
    cudaGetSymbolAddress((void**)&p_agg, g_agg);
    cudaGetSymbolAddress((void**)&p_deg, g_deg);
    cudaGetSymbolAddress((void**)&p_stats, g_stats);
    cudaGetSymbolAddress((void**)&p_bnA, g_bnA);
    cudaGetSymbolAddress((void**)&p_bnC, g_bnC);

    cudaFuncSetAttribute(mlp_kernel, cudaFuncAttributeMaxDynamicSharedMemorySize, SMEM_BYTES);
    cudaFuncSetAttribute(node_final_kernel, cudaFuncAttributeMaxDynamicSharedMemorySize, SMEM_BYTES);
    cudaFuncSetAttribute(final_edge_kernel, cudaFuncAttributeMaxDynamicSharedMemorySize, SMEM_BYTES);

    cudaMemsetAsync(p_stats, 0, 5 * 2 * 128 * sizeof(float), 0);
    cudaMemsetAsync(p_agg, 0, (size_t)NODE_CAP * D * sizeof(float), 0);
    cudaMemsetAsync(p_deg, 0, NODE_CAP * sizeof(float), 0);

    int egrid = (E + 127) / 128;
    int ngrid = (N + 127) / 128;

    // edge MLP0
    mlp_kernel<<<egrid, 256, SMEM_BYTES>>>(edata, W1s, b1s, W2s, b2s,
                                           p_t1, E, 0, 0, nullptr, nullptr, nullptr);
    finalize_bn<<<1, 128>>>(0, (float)E, gs, bts);
    // edge MLP1 (input = BN0(t1))
    mlp_kernel<<<egrid, 256, SMEM_BYTES>>>(p_t1, W1s + 16384, b1s + 128,
                                           W2s + 16384, b2s + 128,
                                           p_u, E, 1, 1, p_bnA, p_bnC, nullptr);
    finalize_bn<<<1, 128>>>(1, (float)E, gs + 128, bts + 128);
    // h_e = BN0(t1) + BN1(u); scatter-sum + degree
    scatter_kernel<<<2048, 256>>>(dst, E);
    // node MLP2 (input = agg / max(deg,1))
    mlp_kernel<<<ngrid, 256, SMEM_BYTES>>>(p_agg, W1s + 2 * 16384, b1s + 256,
                                           W2s + 2 * 16384, b2s + 256,
                                           p_v, N, 2, 2, nullptr, nullptr, p_deg);
    finalize_bn<<<1, 128>>>(2, (float)N, gs + 256, bts + 256);
    // node MLP3 (input = BN2(v))
    mlp_kernel<<<ngrid, 256, SMEM_BYTES>>>(p_v, W1s + 3 * 16384, b1s + 384,
                                           W2s + 3 * 16384, b2s + 384,
                                           p_w2, N, 1, 3, p_bnA + 256, p_bnC + 256, nullptr);
    finalize_bn<<<1, 128>>>(3, (float)N, gs + 384, bts + 384);
    // h_n final + per-node partial products through eW1 src/dst slices
    node_final_kernel<<<ngrid, 256, SMEM_BYTES>>>(eW1, N);
    // final edge MLP -> d_out (pre-BN)
    final_edge_kernel<<<egrid, 256, SMEM_BYTES>>>(edata, src, dst, eW1, eb1,
                                                  eW2, eb2, (float*)d_out, E);
    finalize_bn<<<1, 128>>>(4, (float)E, eg, ebt);
    int n4 = E * (D / 4);
    norm_out_kernel<<<(n4 + 255) / 256, 256>>>((float*)d_out, n4);
}

// round 4
// speedup vs baseline: 1.5645x; 1.5645x over previous
#include <cuda_runtime.h>
#include <cuda_bf16.h>
#include <math.h>
#include <stdint.h>

#define D 128
#define EPS 1e-5f
#define PADX 132
#define NODE_CAP 20096
#define E_MAX 640000

static const int SMEM_BYTES = (128 * PADX + 128 * 128) * 4;  // SIMT kernels
// TC kernel smem: Ah,Al,Wh,Wl each 128 rows x 272 bytes (128 bf16 + 8 pad)
#define TILE_PITCH 272
#define TILE_BYTES_PAD (128 * TILE_PITCH)  // 34816
static const int TC_SMEM = 4 * TILE_BYTES_PAD;  // 139264

// ---------------- scratch ----------------
__device__ float g_t1[(size_t)E_MAX * D];
__device__ float g_u [(size_t)E_MAX * D];
__device__ float g_v [(size_t)NODE_CAP * D];
__device__ float g_w [(size_t)NODE_CAP * D];
__device__ float g_P1[(size_t)NODE_CAP * D];
__device__ float g_P2[(size_t)NODE_CAP * D];
__device__ float g_agg[(size_t)NODE_CAP * D];
__device__ float g_deg[NODE_CAP];
__device__ float g_stats[5 * 2 * 128];
__device__ float g_bnA[5 * 128];
__device__ float g_bnC[5 * 128];
// prepped weights: 6 matrices x (hi,lo), each [n][k] bf16 128x128 = 32KB
__device__ unsigned char g_wprep[12 * 32768];

// ---------------- helpers ----------------
__device__ __forceinline__ float elu1(float x) { return x > 0.f ? x : expm1f(x); }

__device__ __forceinline__ uint32_t smem_u32(const void* p) {
    uint32_t a;
    asm("{ .reg .u64 t; cvta.to.shared.u64 t, %1; cvt.u32.u64 %0, t; }" : "=r"(a) : "l"(p));
    return a;
}

__device__ __forceinline__ uint32_t pk2(__nv_bfloat16 a, __nv_bfloat16 b) {
    __nv_bfloat162 t = __halves2bfloat162(a, b);
    return *reinterpret_cast<uint32_t*>(&t);
}

__device__ __forceinline__ void split2(float a, float b, uint32_t& hi, uint32_t& lo) {
    __nv_bfloat16 ha = __float2bfloat16(a), hb = __float2bfloat16(b);
    float la = a - __bfloat162float(ha);
    float lb = b - __bfloat162float(hb);
    hi = pk2(ha, hb);
    lo = pk2(__float2bfloat16(la), __float2bfloat16(lb));
}

// split 8 fp32 -> bf16 hi/lo, 16B stores to padded tiles
__device__ __forceinline__ void split_store8(const float* v, unsigned char* Ah,
                                             unsigned char* Al, uint32_t off) {
    uint32_t hw[4], lw[4];
#pragma unroll
    for (int i = 0; i < 4; i++) split2(v[2 * i], v[2 * i + 1], hw[i], lw[i]);
    *reinterpret_cast<uint4*>(Ah + off) = make_uint4(hw[0], hw[1], hw[2], hw[3]);
    *reinterpret_cast<uint4*>(Al + off) = make_uint4(lw[0], lw[1], lw[2], lw[3]);
}

__device__ __forceinline__ void ldm4(uint32_t* r, uint32_t a) {
    asm volatile("ldmatrix.sync.aligned.m8n8.x4.shared.b16 {%0,%1,%2,%3}, [%4];"
                 : "=r"(r[0]), "=r"(r[1]), "=r"(r[2]), "=r"(r[3]) : "r"(a));
}

__device__ __forceinline__ void mma16816(float* c, const uint32_t* a, const uint32_t* b) {
    asm volatile(
        "mma.sync.aligned.m16n8k16.row.col.f32.bf16.bf16.f32 "
        "{%0,%1,%2,%3}, {%4,%5,%6,%7}, {%8,%9}, {%0,%1,%2,%3};"
        : "+f"(c[0]), "+f"(c[1]), "+f"(c[2]), "+f"(c[3])
        : "r"(a[0]), "r"(a[1]), "r"(a[2]), "r"(a[3]), "r"(b[0]), "r"(b[1]));
}

// 3-split warp GEMM: acc += Ah@Wh + Al@Wh + Ah@Wl  (warp tile m32 x n64)
__device__ __forceinline__ void warp_gemm3(uint32_t Ah, uint32_t Al,
                                           uint32_t Wh, uint32_t Wl,
                                           int lane, int wm, int wn,
                                           float acc[2][8][4]) {
    const int arow = lane & 15;
    const int kA = ((lane >> 4) << 3) * 2;               // byte k-offset
    const int brow = ((lane >> 4) << 3) + (lane & 7);
    const int kB = (((lane >> 3) & 1) << 3) * 2;
    const uint32_t aoff0 = (uint32_t)((wm * 32 + arow) * TILE_PITCH) + kA;
    const uint32_t aoff1 = aoff0 + 16 * TILE_PITCH;
    uint32_t boff[4];
#pragma unroll
    for (int p = 0; p < 4; p++)
        boff[p] = (uint32_t)((wn * 64 + p * 16 + brow) * TILE_PITCH) + kB;

#pragma unroll
    for (int s = 0; s < 3; s++) {
        uint32_t A = (s == 1) ? Al : Ah;
        uint32_t W = (s == 2) ? Wl : Wh;
#pragma unroll
        for (int k0 = 0; k0 < 128; k0 += 16) {
            uint32_t a0[4], a1[4], b[4][4];
            ldm4(a0, A + aoff0 + k0 * 2);
            ldm4(a1, A + aoff1 + k0 * 2);
#pragma unroll
            for (int p = 0; p < 4; p++) ldm4(b[p], W + boff[p] + k0 * 2);
#pragma unroll
            for (int j = 0; j < 8; j++) {
                const uint32_t* bj = &b[j >> 1][(j & 1) * 2];
                mma16816(acc[0][j], a0, bj);
                mma16816(acc[1][j], a1, bj);
            }
        }
    }
}

// ---------------- weight prep: transpose + bf16 split ----------------
// m: 0:W1s[0] 1:W2s[0] 2:W1s[1] 3:W2s[1] 4:eW1[0:128,:] 5:eW2
// output layout [n][k]: Wt[n][k] = W[k][n]  (B operand, "col" major for mma)
__global__ void prep_weights(const float* __restrict__ W1s, const float* __restrict__ W2s,
                             const float* __restrict__ eW1, const float* __restrict__ eW2)
{
    int idx = blockIdx.x * 256 + threadIdx.x;
    if (idx >= 6 * 16384) return;
    int m = idx >> 14;
    int e = idx & 16383;
    int n = e >> 7, k = e & 127;
    const float* W;
    switch (m) {
        case 0: W = W1s; break;
        case 1: W = W2s; break;
        case 2: W = W1s + 16384; break;
        case 3: W = W2s + 16384; break;
        case 4: W = eW1; break;
        default: W = eW2; break;
    }
    float v = W[k * 128 + n];
    __nv_bfloat16 h = __float2bfloat16(v);
    __nv_bfloat16 l = __float2bfloat16(v - __bfloat162float(h));
    *reinterpret_cast<__nv_bfloat16*>(g_wprep + (size_t)(2 * m) * 32768 + (size_t)e * 2) = h;
    *reinterpret_cast<__nv_bfloat16*>(g_wprep + (size_t)(2 * m + 1) * 32768 + (size_t)e * 2) = l;
}

// ---------------- tensor-core fused MLP over 128-row tiles ----------------
template <bool GATHER>
__global__ void __launch_bounds__(256, 1)
tc_mlp_tpl(const float* __restrict__ X, int m1, int m2,
           const float* __restrict__ B1, const float* __restrict__ B2,
           float* __restrict__ out, int nrows, int mode, int stage,
           const float* __restrict__ preA, const float* __restrict__ preC,
           const int* __restrict__ srcI, const int* __restrict__ dstI)
{
    extern __shared__ unsigned char smem[];
    unsigned char* Ah = smem;
    unsigned char* Al = smem + TILE_BYTES_PAD;
    unsigned char* Wh = smem + 2 * TILE_BYTES_PAD;
    unsigned char* Wl = smem + 3 * TILE_BYTES_PAD;
    __shared__ float sB1[128], sB2[128], sPA[128], sPC[128];
    __shared__ int sSrc[128], sDst[128];

    const int tid = threadIdx.x, wid = tid >> 5, lane = tid & 31;
    const int wm = wid & 3, wn = wid >> 2;       // warp tile: rows 32*wm, cols 64*wn
    const int g = lane >> 2, tig = lane & 3;
    const int row0 = blockIdx.x * 128;

    if (tid < 128) {
        sB1[tid] = B1[tid];
        sB2[tid] = B2[tid];
        if (mode == 1) { sPA[tid] = preA[tid]; sPC[tid] = preC[tid]; }
        if (GATHER) {
            int gr = row0 + tid;
            sSrc[tid] = (gr < nrows) ? srcI[gr] : 0;
            sDst[tid] = (gr < nrows) ? dstI[gr] : 0;
        }
    }
    __syncthreads();  // sPA/sPC (and sB/sSrc) must be visible to ALL threads

    // ---- load + split A tile (each thread: one half-row = 64 floats) ----
    {
        int r = tid >> 1, half = tid & 1;
        int gr = row0 + r;
        const float* xr = X + (size_t)gr * D + half * 64;
#pragma unroll
        for (int gq = 0; gq < 8; gq++) {
            int k0 = half * 64 + gq * 8;
            float v[8];
            if (gr < nrows) {
                float4 a = *reinterpret_cast<const float4*>(xr + gq * 8);
                float4 b = *reinterpret_cast<const float4*>(xr + gq * 8 + 4);
                v[0] = a.x; v[1] = a.y; v[2] = a.z; v[3] = a.w;
                v[4] = b.x; v[5] = b.y; v[6] = b.z; v[7] = b.w;
                if (mode == 1) {
#pragma unroll
                    for (int i = 0; i < 8; i++) v[i] = v[i] * sPA[k0 + i] + sPC[k0 + i];
                }
            } else {
#pragma unroll
                for (int i = 0; i < 8; i++) v[i] = 0.f;
            }
            split_store8(v, Ah, Al, (uint32_t)(r * TILE_PITCH + k0 * 2));
        }
    }
    // ---- load W1 tiles (prepped [n][k], add row pad) ----
    {
        const uint4* gh = reinterpret_cast<const uint4*>(g_wprep + (size_t)(2 * m1) * 32768);
        const uint4* gl = gh + 2048;
#pragma unroll
        for (int t = 0; t < 8; t++) {
            int idx = tid + 256 * t;
            int rr = idx >> 4, ch = idx & 15;
            uint32_t off = (uint32_t)(rr * TILE_PITCH + ch * 16);
            *reinterpret_cast<uint4*>(Wh + off) = gh[idx];
            *reinterpret_cast<uint4*>(Wl + off) = gl[idx];
        }
    }
    __syncthreads();

    const uint32_t uAh = smem_u32(Ah), uAl = smem_u32(Al);
    const uint32_t uWh = smem_u32(Wh), uWl = smem_u32(Wl);

    // ---- GEMM1 ----
    float acc[2][8][4];
#pragma unroll
    for (int i = 0; i < 2; i++)
#pragma unroll
        for (int j = 0; j < 8; j++) {
            int col = wn * 64 + j * 8 + 2 * tig;
            acc[i][j][0] = sB1[col]; acc[i][j][1] = sB1[col + 1];
            acc[i][j][2] = sB1[col]; acc[i][j][3] = sB1[col + 1];
        }
    warp_gemm3(uAh, uAl, uWh, uWl, lane, wm, wn, acc);
    __syncthreads();

    // ---- epilogue1: h1 = elu(acc [+ P1[src]+P2[dst]]); re-split into A ----
#pragma unroll
    for (int i = 0; i < 2; i++) {
        int r0 = wm * 32 + i * 16 + g;
        int r1 = r0 + 8;
#pragma unroll
        for (int j = 0; j < 8; j++) {
            int col = wn * 64 + j * 8 + 2 * tig;
            float v0 = acc[i][j][0], v1 = acc[i][j][1];
            float v2 = acc[i][j][2], v3 = acc[i][j][3];
            if (GATHER) {
                const float2 p1a = *reinterpret_cast<const float2*>(g_P1 + (size_t)sSrc[r0] * D + col);
                const float2 p2a = *reinterpret_cast<const float2*>(g_P2 + (size_t)sDst[r0] * D + col);
                const float2 p1b = *reinterpret_cast<const float2*>(g_P1 + (size_t)sSrc[r1] * D + col);
                const float2 p2b = *reinterpret_cast<const float2*>(g_P2 + (size_t)sDst[r1] * D + col);
                v0 += p1a.x + p2a.x; v1 += p1a.y + p2a.y;
                v2 += p1b.x + p2b.x; v3 += p1b.y + p2b.y;
            }
            v0 = elu1(v0); v1 = elu1(v1); v2 = elu1(v2); v3 = elu1(v3);
            uint32_t hi, lo;
            split2(v0, v1, hi, lo);
            *reinterpret_cast<uint32_t*>(Ah + r0 * TILE_PITCH + col * 2) = hi;
            *reinterpret_cast<uint32_t*>(Al + r0 * TILE_PITCH + col * 2) = lo;
            split2(v2, v3, hi, lo);
            *reinterpret_cast<uint32_t*>(Ah + r1 * TILE_PITCH + col * 2) = hi;
            *reinterpret_cast<uint32_t*>(Al + r1 * TILE_PITCH + col * 2) = lo;
        }
    }
    // ---- load W2 tiles ----
    {
        const uint4* gh = reinterpret_cast<const uint4*>(g_wprep + (size_t)(2 * m2) * 32768);
        const uint4* gl = gh + 2048;
#pragma unroll
        for (int t = 0; t < 8; t++) {
            int idx = tid + 256 * t;
            int rr = idx >> 4, ch = idx & 15;
            uint32_t off = (uint32_t)(rr * TILE_PITCH + ch * 16);
            *reinterpret_cast<uint4*>(Wh + off) = gh[idx];
            *reinterpret_cast<uint4*>(Wl + off) = gl[idx];
        }
    }
    __syncthreads();

    // ---- GEMM2 ----
#pragma unroll
    for (int i = 0; i < 2; i++)
#pragma unroll
        for (int j = 0; j < 8; j++) {
            int col = wn * 64 + j * 8 + 2 * tig;
            acc[i][j][0] = sB2[col]; acc[i][j][1] = sB2[col + 1];
            acc[i][j][2] = sB2[col]; acc[i][j][3] = sB2[col + 1];
        }
    warp_gemm3(uAh, uAl, uWh, uWl, lane, wm, wn, acc);
    __syncthreads();

    // ---- epilogue2: h2 = elu(acc) -> gmem + smem scratch (stats) ----
    float* scratch = reinterpret_cast<float*>(Wh);  // 128 x 132 fp32 = 67584 B
#pragma unroll
    for (int i = 0; i < 2; i++) {
        int r0 = wm * 32 + i * 16 + g;
        int r1 = r0 + 8;
        int gr0 = row0 + r0, gr1 = row0 + r1;
        bool va = gr0 < nrows, vb = gr1 < nrows;
#pragma unroll
        for (int j = 0; j < 8; j++) {
            int col = wn * 64 + j * 8 + 2 * tig;
            float v0 = va ? elu1(acc[i][j][0]) : 0.f;
            float v1 = va ? elu1(acc[i][j][1]) : 0.f;
            float v2 = vb ? elu1(acc[i][j][2]) : 0.f;
            float v3 = vb ? elu1(acc[i][j][3]) : 0.f;
            *reinterpret_cast<float2*>(scratch + r0 * 132 + col) = make_float2(v0, v1);
            *reinterpret_cast<float2*>(scratch + r1 * 132 + col) = make_float2(v2, v3);
            if (va) *reinterpret_cast<float2*>(out + (size_t)gr0 * D + col) = make_float2(v0, v1);
            if (vb) *reinterpret_cast<float2*>(out + (size_t)gr1 * D + col) = make_float2(v2, v3);
        }
    }
    __syncthreads();

    if (tid < 128) {
        float s = 0.f, q = 0.f;
#pragma unroll 4
        for (int r = 0; r < 128; r++) {
            float vv = scratch[r * 132 + tid];
            s += vv; q += vv * vv;
        }
        atomicAdd(&g_stats[stage * 256 + tid], s);
        atomicAdd(&g_stats[stage * 256 + 128 + tid], q);
    }
}

// ---------------- SIMT path for small node stages ----------------
__device__ __forceinline__ float2 ffma2(float2 d, float2 a, float2 b) {
    asm("fma.rn.f32x2 %0, %1, %2, %0;"
        : "+l"(reinterpret_cast<unsigned long long&>(d))
        : "l"(reinterpret_cast<unsigned long long&>(a)),
          "l"(reinterpret_cast<unsigned long long&>(b)));
    return d;
}

__device__ __forceinline__ void gemm_tile(const float* __restrict__ Xs,
                                          const float* __restrict__ Ws,
                                          float2 acc[8][4], int tx, int ty) {
#pragma unroll 2
    for (int k = 0; k < 128; k++) {
        float xv[8];
        float2 ww[4];
#pragma unroll
        for (int j = 0; j < 8; j++) xv[j] = Xs[(ty + 16 * j) * PADX + k];
#pragma unroll
        for (int p = 0; p < 4; p++) {
            float w0 = Ws[k * 128 + tx + 32 * p];
            float w1 = Ws[k * 128 + tx + 32 * p + 16];
            ww[p] = make_float2(w0, w1);
        }
#pragma unroll
        for (int j = 0; j < 8; j++) {
            float2 xx = make_float2(xv[j], xv[j]);
#pragma unroll
            for (int p = 0; p < 4; p++) acc[j][p] = ffma2(acc[j][p], xx, ww[p]);
        }
    }
}

__global__ void __launch_bounds__(256, 1)
mlp_kernel(const float* __restrict__ X,
           const float* __restrict__ W1, const float* __restrict__ B1,
           const float* __restrict__ W2, const float* __restrict__ B2,
           float* __restrict__ out, int nrows, int mode, int stage,
           const float* __restrict__ preA, const float* __restrict__ preC,
           const float* __restrict__ degp)
{
    extern __shared__ float smemf[];
    float* Xs = smemf;
    float* Ws = smemf + 128 * PADX;
    __shared__ float sB[128];
    __shared__ float sPA[128], sPC[128], sDeg[128];

    const int tid = threadIdx.x;
    const int tx = tid & 15, ty = tid >> 4;
    const int row0 = blockIdx.x * 128;

    if (tid < 128) {
        sB[tid] = B1[tid];
        if (mode == 1) { sPA[tid] = preA[tid]; sPC[tid] = preC[tid]; }
        if (mode == 2) {
            int r = row0 + tid;
            sDeg[tid] = (r < nrows) ? (1.f / fmaxf(degp[r], 1.f)) : 0.f;
        }
    }
    __syncthreads();

#pragma unroll
    for (int t = 0; t < 16; t++) {
        int idx = tid + t * 256;
        int r = idx >> 5;
        int c4 = (idx & 31) << 2;
        int gr = row0 + r;
        float4 v = make_float4(0.f, 0.f, 0.f, 0.f);
        if (gr < nrows) {
            v = *reinterpret_cast<const float4*>(X + (size_t)gr * D + c4);
            if (mode == 1) {
                v.x = v.x * sPA[c4] + sPC[c4];
                v.y = v.y * sPA[c4 + 1] + sPC[c4 + 1];
                v.z = v.z * sPA[c4 + 2] + sPC[c4 + 2];
                v.w = v.w * sPA[c4 + 3] + sPC[c4 + 3];
            } else if (mode == 2) {
                float s = sDeg[r];
                v.x *= s; v.y *= s; v.z *= s; v.w *= s;
            }
        }
        *reinterpret_cast<float4*>(Xs + r * PADX + c4) = v;
        reinterpret_cast<float4*>(Ws)[idx] = reinterpret_cast<const float4*>(W1)[idx];
    }
    __syncthreads();

    float2 acc[8][4];
#pragma unroll
    for (int j = 0; j < 8; j++)
#pragma unroll
        for (int p = 0; p < 4; p++)
            acc[j][p] = make_float2(sB[tx + 32 * p], sB[tx + 32 * p + 16]);

    gemm_tile(Xs, Ws, acc, tx, ty);
#pragma unroll
    for (int j = 0; j < 8; j++)
#pragma unroll
        for (int p = 0; p < 4; p++) {
            acc[j][p].x = elu1(acc[j][p].x);
            acc[j][p].y = elu1(acc[j][p].y);
        }
    __syncthreads();

#pragma unroll
    for (int j = 0; j < 8; j++) {
        int r = ty + 16 * j;
#pragma unroll
        for (int p = 0; p < 4; p++) {
            Xs[r * PADX + tx + 32 * p]      = acc[j][p].x;
            Xs[r * PADX + tx + 32 * p + 16] = acc[j][p].y;
        }
    }
#pragma unroll
    for (int t = 0; t < 16; t++) {
        int idx = tid + t * 256;
        reinterpret_cast<float4*>(Ws)[idx] = reinterpret_cast<const float4*>(W2)[idx];
    }
    if (tid < 128) sB[tid] = B2[tid];
    __syncthreads();

#pragma unroll
    for (int j = 0; j < 8; j++)
#pragma unroll
        for (int p = 0; p < 4; p++)
            acc[j][p] = make_float2(sB[tx + 32 * p], sB[tx + 32 * p + 16]);

    gemm_tile(Xs, Ws, acc, tx, ty);
#pragma unroll
    for (int j = 0; j < 8; j++)
#pragma unroll
        for (int p = 0; p < 4; p++) {
            acc[j][p].x = elu1(acc[j][p].x);
            acc[j][p].y = elu1(acc[j][p].y);
        }
    __syncthreads();

#pragma unroll
    for (int j = 0; j < 8; j++) {
        int r = ty + 16 * j;
        int gr = row0 + r;
        bool valid = gr < nrows;
#pragma unroll
        for (int p = 0; p < 4; p++) {
            int c0 = tx + 32 * p, c1 = c0 + 16;
            float vx = valid ? acc[j][p].x : 0.f;
            float vy = valid ? acc[j][p].y : 0.f;
            Xs[r * PADX + c0] = vx;
            Xs[r * PADX + c1] = vy;
            if (valid) {
                out[(size_t)gr * D + c0] = vx;
                out[(size_t)gr * D + c1] = vy;
            }
        }
    }
    __syncthreads();

    if (tid < 128) {
        float s = 0.f, q = 0.f;
#pragma unroll 4
        for (int r = 0; r < 128; r++) {
            float vv = Xs[r * PADX + tid];
            s += vv; q += vv * vv;
        }
        atomicAdd(&g_stats[stage * 256 + tid], s);
        atomicAdd(&g_stats[stage * 256 + 128 + tid], q);
    }
}

__global__ void finalize_bn(int stage, float cnt,
                            const float* __restrict__ g, const float* __restrict__ bt)
{
    int j = threadIdx.x;
    float s1 = g_stats[stage * 256 + j];
    float s2 = g_stats[stage * 256 + 128 + j];
    float mu = s1 / cnt;
    float var = s2 / cnt - mu * mu;
    float a = g[j] * rsqrtf(var + EPS);
    g_bnA[stage * 128 + j] = a;
    g_bnC[stage * 128 + j] = bt[j] - mu * a;
}

__global__ void __launch_bounds__(256)
scatter_kernel(const int* __restrict__ dst, int nedges)
{
    int lane = threadIdx.x & 31;
    int warp = (blockIdx.x * 256 + threadIdx.x) >> 5;
    int nw = (gridDim.x * 256) >> 5;
    float4 A0 = reinterpret_cast<const float4*>(g_bnA)[lane];
    float4 C0 = reinterpret_cast<const float4*>(g_bnC)[lane];
    float4 A1 = reinterpret_cast<const float4*>(g_bnA + 128)[lane];
    float4 C1 = reinterpret_cast<const float4*>(g_bnC + 128)[lane];
    for (int e = warp; e < nedges; e += nw) {
        int d = __ldg(dst + e);
        float4 t = reinterpret_cast<const float4*>(g_t1 + (size_t)e * D)[lane];
        float4 u = reinterpret_cast<const float4*>(g_u + (size_t)e * D)[lane];
        float4 h;
        h.x = (t.x * A0.x + C0.x) + (u.x * A1.x + C1.x);
        h.y = (t.y * A0.y + C0.y) + (u.y * A1.y + C1.y);
        h.z = (t.z * A0.z + C0.z) + (u.z * A1.z + C1.z);
        h.w = (t.w * A0.w + C0.w) + (u.w * A1.w + C1.w);
        float* base = g_agg + (size_t)d * D + lane * 4;
        atomicAdd(base + 0, h.x);
        atomicAdd(base + 1, h.y);
        atomicAdd(base + 2, h.z);
        atomicAdd(base + 3, h.w);
        if (lane == 0) atomicAdd(&g_deg[d], 1.f);
    }
}

__global__ void __launch_bounds__(256, 1)
node_final_kernel(const float* __restrict__ eW1, int nrows)
{
    extern __shared__ float smemf[];
    float* Hs = smemf;
    float* Ws = smemf + 128 * PADX;
    const int tid = threadIdx.x;
    const int tx = tid & 15, ty = tid >> 4;
    const int row0 = blockIdx.x * 128;

#pragma unroll
    for (int t = 0; t < 16; t++) {
        int idx = tid + t * 256;
        int r = idx >> 5;
        int c4 = (idx & 31) << 2;
        int gr = row0 + r;
        float4 h = make_float4(0.f, 0.f, 0.f, 0.f);
        if (gr < nrows) {
            float4 v = *reinterpret_cast<const float4*>(g_v + (size_t)gr * D + c4);
            float4 w = *reinterpret_cast<const float4*>(g_w + (size_t)gr * D + c4);
            float4 A2 = reinterpret_cast<const float4*>(g_bnA + 256)[c4 >> 2];
            float4 C2 = reinterpret_cast<const float4*>(g_bnC + 256)[c4 >> 2];
            float4 A3 = reinterpret_cast<const float4*>(g_bnA + 384)[c4 >> 2];
            float4 C3 = reinterpret_cast<const float4*>(g_bnC + 384)[c4 >> 2];
            h.x = (w.x * A3.x + C3.x) + (v.x * A2.x + C2.x);
            h.y = (w.y * A3.y + C3.y) + (v.y * A2.y + C2.y);
            h.z = (w.z * A3.z + C3.z) + (v.z * A2.z + C2.z);
            h.w = (w.w * A3.w + C3.w) + (v.w * A2.w + C2.w);
        }
        *reinterpret_cast<float4*>(Hs + r * PADX + c4) = h;
        reinterpret_cast<float4*>(Ws)[idx] =
            reinterpret_cast<const float4*>(eW1 + 128 * 128)[idx];
    }
    __syncthreads();

    float2 acc[8][4];
#pragma unroll
    for (int j = 0; j < 8; j++)
#pragma unroll
        for (int p = 0; p < 4; p++) acc[j][p] = make_float2(0.f, 0.f);
    gemm_tile(Hs, Ws, acc, tx, ty);
    __syncthreads();

#pragma unroll
    for (int j = 0; j < 8; j++) {
        int gr = row0 + ty + 16 * j;
        if (gr < nrows)
#pragma unroll
            for (int p = 0; p < 4; p++) {
                g_P1[(size_t)gr * D + tx + 32 * p]      = acc[j][p].x;
                g_P1[(size_t)gr * D + tx + 32 * p + 16] = acc[j][p].y;
            }
    }
#pragma unroll
    for (int t = 0; t < 16; t++) {
        int idx = tid + t * 256;
        reinterpret_cast<float4*>(Ws)[idx] =
            reinterpret_cast<const float4*>(eW1 + 256 * 128)[idx];
    }
    __syncthreads();

#pragma unroll
    for (int j = 0; j < 8; j++)
#pragma unroll
        for (int p = 0; p < 4; p++) acc[j][p] = make_float2(0.f, 0.f);
    gemm_tile(Hs, Ws, acc, tx, ty);

#pragma unroll
    for (int j = 0; j < 8; j++) {
        int gr = row0 + ty + 16 * j;
        if (gr < nrows)
#pragma unroll
            for (int p = 0; p < 4; p++) {
                g_P2[(size_t)gr * D + tx + 32 * p]      = acc[j][p].x;
                g_P2[(size_t)gr * D + tx + 32 * p + 16] = acc[j][p].y;
            }
    }
}

__global__ void norm_out_kernel(float* __restrict__ out, int n4)
{
    int idx = blockIdx.x * blockDim.x + threadIdx.x;
    if (idx >= n4) return;
    int cv = idx & 31;
    float4 A = reinterpret_cast<const float4*>(g_bnA + 512)[cv];
    float4 C = reinterpret_cast<const float4*>(g_bnC + 512)[cv];
    float4 v = reinterpret_cast<float4*>(out)[idx];
    v.x = v.x * A.x + C.x;
    v.y = v.y * A.y + C.y;
    v.z = v.z * A.z + C.z;
    v.w = v.w * A.w + C.w;
    reinterpret_cast<float4*>(out)[idx] = v;
}

// ---------------- host orchestration ----------------
extern "C" void kernel_launch(void* const* d_in, const int* in_sizes, int n_in,
                              void* d_out, int out_size)
{
    if (n_in < 15) return;
    const float* edata = (const float*)d_in[0];
    const int*   src   = (const int*)d_in[1];
    const int*   dst   = (const int*)d_in[2];
    int w = (n_in >= 16) ? 4 : 3;
    const float* W1s = (const float*)d_in[w + 0];
    const float* b1s = (const float*)d_in[w + 1];
    const float* W2s = (const float*)d_in[w + 2];
    const float* b2s = (const float*)d_in[w + 3];
    const float* gs  = (const float*)d_in[w + 4];
    const float* bts = (const float*)d_in[w + 5];
    const float* eW1 = (const float*)d_in[w + 6];
    const float* eb1 = (const float*)d_in[w + 7];
    const float* eW2 = (const float*)d_in[w + 8];
    const float* eb2 = (const float*)d_in[w + 9];
    const float* eg  = (const float*)d_in[w + 10];
    const float* ebt = (const float*)d_in[w + 11];

    int E = in_sizes[0] / D;
    int N = 20000;

    float *p_t1, *p_u, *p_v, *p_w2, *p_agg, *p_deg, *p_stats, *p_bnA, *p_bnC;
    cudaGetSymbolAddress((void**)&p_t1, g_t1);
    cudaGetSymbolAddress((void**)&p_u, g_u);
    cudaGetSymbolAddress((void**)&p_v, g_v);
    cudaGetSymbolAddress((void**)&p_w2, g_w);
    cudaGetSymbolAddress((void**)&p_agg, g_agg);
    cudaGetSymbolAddress((void**)&p_deg, g_deg);
    cudaGetSymbolAddress((void**)&p_stats, g_stats);
    cudaGetSymbolAddress((void**)&p_bnA, g_bnA);
    cudaGetSymbolAddress((void**)&p_bnC, g_bnC);

    cudaFuncSetAttribute(mlp_kernel, cudaFuncAttributeMaxDynamicSharedMemorySize, SMEM_BYTES);
    cudaFuncSetAttribute(node_final_kernel, cudaFuncAttributeMaxDynamicSharedMemorySize, SMEM_BYTES);
    cudaFuncSetAttribute(tc_mlp_tpl<false>, cudaFuncAttributeMaxDynamicSharedMemorySize, TC_SMEM);
    cudaFuncSetAttribute(tc_mlp_tpl<true>,  cudaFuncAttributeMaxDynamicSharedMemorySize, TC_SMEM);

    cudaMemsetAsync(p_stats, 0, 5 * 2 * 128 * sizeof(float), 0);
    cudaMemsetAsync(p_agg, 0, (size_t)NODE_CAP * D * sizeof(float), 0);
    cudaMemsetAsync(p_deg, 0, NODE_CAP * sizeof(float), 0);

    int egrid = (E + 127) / 128;
    int ngrid = (N + 127) / 128;

    // weight prep: transpose + bf16 hi/lo split
    prep_weights<<<(6 * 16384 + 255) / 256, 256>>>(W1s, W2s, eW1, eW2);

    // edge MLP0 (tensor cores)
    tc_mlp_tpl<false><<<egrid, 256, TC_SMEM>>>(edata, 0, 1, b1s, b2s,
                                               p_t1, E, 0, 0, nullptr, nullptr,
                                               nullptr, nullptr);
    finalize_bn<<<1, 128>>>(0, (float)E, gs, bts);
    // edge MLP1 (input = BN0(t1), folded affine)
    tc_mlp_tpl<false><<<egrid, 256, TC_SMEM>>>(p_t1, 2, 3, b1s + 128, b2s + 128,
                                               p_u, E, 1, 1, p_bnA, p_bnC,
                                               nullptr, nullptr);
    finalize_bn<<<1, 128>>>(1, (float)E, gs + 128, bts + 128);
    // h_e = BN0(t1)+BN1(u); scatter-sum + degree
    scatter_kernel<<<2048, 256>>>(dst, E);
    // node MLP2 (input = agg / max(deg,1)) — SIMT
    mlp_kernel<<<ngrid, 256, SMEM_BYTES>>>(p_agg, W1s + 2 * 16384, b1s + 256,
                                           W2s + 2 * 16384, b2s + 256,
                                           p_v, N, 2, 2, nullptr, nullptr, p_deg);
    finalize_bn<<<1, 128>>>(2, (float)N, gs + 256, bts + 256);
    // node MLP3 — SIMT
    mlp_kernel<<<ngrid, 256, SMEM_BYTES>>>(p_v, W1s + 3 * 16384, b1s + 384,
                                           W2s + 3 * 16384, b2s + 384,
                                           p_w2, N, 1, 3, p_bnA + 256, p_bnC + 256, nullptr);
    finalize_bn<<<1, 128>>>(3, (float)N, gs + 384, bts + 384);
    // h_n + per-node partials P1/P2 through eW1 src/dst slices — SIMT
    node_final_kernel<<<ngrid, 256, SMEM_BYTES>>>(eW1, N);
    // final edge MLP (tensor cores, with gathers) -> d_out (pre-BN)
    tc_mlp_tpl<true><<<egrid, 256, TC_SMEM>>>(edata, 4, 5, eb1, eb2,
                                              (float*)d_out, E, 0, 4, nullptr, nullptr,
                                              src, dst);
    finalize_bn<<<1, 128>>>(4, (float)E, eg, ebt);
    int n4 = E * (D / 4);
    norm_out_kernel<<<(n4 + 255) / 256, 256>>>((float*)d_out, n4);
}

// round 5
// speedup vs baseline: 1.8573x; 1.1871x over previous
#include <cuda_runtime.h>
#include <cuda_bf16.h>
#include <math.h>
#include <stdint.h>

#define D 128
#define EPS 1e-5f
#define PADX 132
#define NODE_CAP 20096
#define E_MAX 640000

static const int SMEM_BYTES = (128 * PADX + 128 * 128) * 4;  // SIMT kernels
// TC kernel smem: 6 tiles (Ah, Al, W1h, W1l, W2h, W2l), 128 rows x 272 bytes
#define TILE_PITCH 272
#define TILE_BYTES_PAD (128 * TILE_PITCH)  // 34816
static const int TC_SMEM = 6 * TILE_BYTES_PAD;  // 208896

// ---------------- scratch ----------------
__device__ float g_t1[(size_t)E_MAX * D];
__device__ float g_u [(size_t)E_MAX * D];
__device__ float g_v [(size_t)NODE_CAP * D];
__device__ float g_w [(size_t)NODE_CAP * D];
__device__ float g_P1[(size_t)NODE_CAP * D];
__device__ float g_P2[(size_t)NODE_CAP * D];
__device__ float g_agg[(size_t)NODE_CAP * D];
__device__ float g_deg[NODE_CAP];
__device__ float g_stats[5 * 2 * 128];
__device__ float g_bnA[5 * 128];
__device__ float g_bnC[5 * 128];
// prepped weights: 6 matrices x (hi,lo), each [n][k] bf16 128x128 = 32KB
__device__ __align__(256) unsigned char g_wprep[12 * 32768];

// ---------------- helpers ----------------
// fast ELU: exp(x)-1 via ex2.approx (abs err ~2^-22, fine for 1e-3 budget)
__device__ __forceinline__ float elu1(float x) {
    float e;
    asm("ex2.approx.f32 %0, %1;" : "=f"(e) : "f"(x * 1.4426950408889634f));
    return x > 0.f ? x : (e - 1.0f);
}

__device__ __forceinline__ uint32_t smem_u32(const void* p) {
    uint32_t a;
    asm("{ .reg .u64 t; cvta.to.shared.u64 t, %1; cvt.u32.u64 %0, t; }" : "=r"(a) : "l"(p));
    return a;
}

#define CP_ASYNC16(dst, src) \
    asm volatile("cp.async.cg.shared.global [%0], [%1], 16;" :: "r"(dst), "l"(src))
#define CP_COMMIT() asm volatile("cp.async.commit_group;")
#define CP_WAIT1()  asm volatile("cp.async.wait_group 1;")
#define CP_WAIT0()  asm volatile("cp.async.wait_group 0;")

// truncation split: hi = a with low 16 bits zeroed (exact bf16), lo = bf16(a - hi)
__device__ __forceinline__ void split2t(float a, float b, uint32_t& hi, uint32_t& lo) {
    uint32_t ai = __float_as_uint(a), bi = __float_as_uint(b);
    hi = __byte_perm(ai, bi, 0x7632);  // {a.hi16 in low, b.hi16 in high}
    float la = a - __uint_as_float(ai & 0xFFFF0000u);
    float lb = b - __uint_as_float(bi & 0xFFFF0000u);
    asm("cvt.rn.bf16x2.f32 %0, %1, %2;" : "=r"(lo) : "f"(lb), "f"(la));
}

// split 8 fp32 -> bf16 hi/lo, 16B stores to padded tiles
__device__ __forceinline__ void split_store8(const float* v, unsigned char* Ah,
                                             unsigned char* Al, uint32_t off) {
    uint32_t hw[4], lw[4];
#pragma unroll
    for (int i = 0; i < 4; i++) split2t(v[2 * i], v[2 * i + 1], hw[i], lw[i]);
    *reinterpret_cast<uint4*>(Ah + off) = make_uint4(hw[0], hw[1], hw[2], hw[3]);
    *reinterpret_cast<uint4*>(Al + off) = make_uint4(lw[0], lw[1], lw[2], lw[3]);
}

__device__ __forceinline__ void ldm4(uint32_t* r, uint32_t a) {
    asm volatile("ldmatrix.sync.aligned.m8n8.x4.shared.b16 {%0,%1,%2,%3}, [%4];"
                 : "=r"(r[0]), "=r"(r[1]), "=r"(r[2]), "=r"(r[3]) : "r"(a));
}

__device__ __forceinline__ void mma16816(float* c, const uint32_t* a, const uint32_t* b) {
    asm volatile(
        "mma.sync.aligned.m16n8k16.row.col.f32.bf16.bf16.f32 "
        "{%0,%1,%2,%3}, {%4,%5,%6,%7}, {%8,%9}, {%0,%1,%2,%3};"
        : "+f"(c[0]), "+f"(c[1]), "+f"(c[2]), "+f"(c[3])
        : "r"(a[0]), "r"(a[1]), "r"(a[2]), "r"(a[3]), "r"(b[0]), "r"(b[1]));
}

// 3-split warp GEMM: acc += Ah@Wh + Al@Wh + Ah@Wl  (warp tile m32 x n64)
__device__ __forceinline__ void warp_gemm3(uint32_t Ah, uint32_t Al,
                                           uint32_t Wh, uint32_t Wl,
                                           int lane, int wm, int wn,
                                           float acc[2][8][4]) {
    const int arow = lane & 15;
    const int kA = ((lane >> 4) << 3) * 2;               // byte k-offset
    const int brow = ((lane >> 4) << 3) + (lane & 7);
    const int kB = (((lane >> 3) & 1) << 3) * 2;
    const uint32_t aoff0 = (uint32_t)((wm * 32 + arow) * TILE_PITCH) + kA;
    const uint32_t aoff1 = aoff0 + 16 * TILE_PITCH;
    uint32_t boff[4];
#pragma unroll
    for (int p = 0; p < 4; p++)
        boff[p] = (uint32_t)((wn * 64 + p * 16 + brow) * TILE_PITCH) + kB;

#pragma unroll
    for (int s = 0; s < 3; s++) {
        uint32_t A = (s == 1) ? Al : Ah;
        uint32_t W = (s == 2) ? Wl : Wh;
#pragma unroll
        for (int k0 = 0; k0 < 128; k0 += 16) {
            uint32_t a0[4], a1[4], b[4][4];
            ldm4(a0, A + aoff0 + k0 * 2);
            ldm4(a1, A + aoff1 + k0 * 2);
#pragma unroll
            for (int p = 0; p < 4; p++) ldm4(b[p], W + boff[p] + k0 * 2);
#pragma unroll
            for (int j = 0; j < 8; j++) {
                const uint32_t* bj = &b[j >> 1][(j & 1) * 2];
                mma16816(acc[0][j], a0, bj);
                mma16816(acc[1][j], a1, bj);
            }
        }
    }
}

// ---------------- weight prep: transpose + bf16 split ----------------
// m: 0:W1s[0] 1:W2s[0] 2:W1s[1] 3:W2s[1] 4:eW1[0:128,:] 5:eW2
__global__ void prep_weights(const float* __restrict__ W1s, const float* __restrict__ W2s,
                             const float* __restrict__ eW1, const float* __restrict__ eW2)
{
    int idx = blockIdx.x * 256 + threadIdx.x;
    if (idx >= 6 * 16384) return;
    int m = idx >> 14;
    int e = idx & 16383;
    int n = e >> 7, k = e & 127;
    const float* W;
    switch (m) {
        case 0: W = W1s; break;
        case 1: W = W2s; break;
        case 2: W = W1s + 16384; break;
        case 3: W = W2s + 16384; break;
        case 4: W = eW1; break;
        default: W = eW2; break;
    }
    float v = W[k * 128 + n];
    __nv_bfloat16 h = __float2bfloat16(v);
    __nv_bfloat16 l = __float2bfloat16(v - __bfloat162float(h));
    *reinterpret_cast<__nv_bfloat16*>(g_wprep + (size_t)(2 * m) * 32768 + (size_t)e * 2) = h;
    *reinterpret_cast<__nv_bfloat16*>(g_wprep + (size_t)(2 * m + 1) * 32768 + (size_t)e * 2) = l;
}

// ---------------- tensor-core fused MLP over 128-row tiles ----------------
template <bool GATHER>
__global__ void __launch_bounds__(256, 1)
tc_mlp_tpl(const float* __restrict__ X, int m1, int m2,
           const float* __restrict__ B1, const float* __restrict__ B2,
           float* __restrict__ out, int nrows, int mode, int stage,
           const float* __restrict__ preA, const float* __restrict__ preC,
           const int* __restrict__ srcI, const int* __restrict__ dstI)
{
    extern __shared__ unsigned char smem[];
    unsigned char* Ah  = smem;
    unsigned char* Al  = smem + TILE_BYTES_PAD;
    unsigned char* W1h = smem + 2 * TILE_BYTES_PAD;
    unsigned char* W1l = smem + 3 * TILE_BYTES_PAD;
    unsigned char* W2h = smem + 4 * TILE_BYTES_PAD;
    unsigned char* W2l = smem + 5 * TILE_BYTES_PAD;
    __shared__ float sB1[128], sB2[128], sPA[128], sPC[128];
    __shared__ int sSrc[128], sDst[128];

    const int tid = threadIdx.x, wid = tid >> 5, lane = tid & 31;
    const int wm = wid & 3, wn = wid >> 2;       // warp tile: rows 32*wm, cols 64*wn
    const int g = lane >> 2, tig = lane & 3;
    const int row0 = blockIdx.x * 128;

    // ---- async W1 prefetch (group old), W2 prefetch (group young) ----
    {
        const char* g1 = (const char*)(g_wprep + (size_t)(2 * m1) * 32768);
        const char* g2 = (const char*)(g_wprep + (size_t)(2 * m2) * 32768);
#pragma unroll
        for (int t = 0; t < 8; t++) {
            int idx = tid + 256 * t;
            uint32_t off = (uint32_t)((idx >> 4) * TILE_PITCH + (idx & 15) * 16);
            CP_ASYNC16(smem_u32(W1h + off), g1 + (size_t)idx * 16);
            CP_ASYNC16(smem_u32(W1l + off), g1 + 32768 + (size_t)idx * 16);
        }
        CP_COMMIT();
#pragma unroll
        for (int t = 0; t < 8; t++) {
            int idx = tid + 256 * t;
            uint32_t off = (uint32_t)((idx >> 4) * TILE_PITCH + (idx & 15) * 16);
            CP_ASYNC16(smem_u32(W2h + off), g2 + (size_t)idx * 16);
            CP_ASYNC16(smem_u32(W2l + off), g2 + 32768 + (size_t)idx * 16);
        }
        CP_COMMIT();
    }

    if (tid < 128) {
        sB1[tid] = B1[tid];
        sB2[tid] = B2[tid];
        if (mode == 1) { sPA[tid] = preA[tid]; sPC[tid] = preC[tid]; }
        if (GATHER) {
            int gr = row0 + tid;
            sSrc[tid] = (gr < nrows) ? srcI[gr] : 0;
            sDst[tid] = (gr < nrows) ? dstI[gr] : 0;
        }
    }
    __syncthreads();  // sPA/sPC visible before A-load uses them

    // ---- coalesced load + split A tile (8B-float groups, lane-contiguous) ----
#pragma unroll
    for (int t = 0; t < 8; t++) {
        int q = tid + 256 * t;        // 2048 groups of 8 floats
        int r = q >> 4;
        int kp = (q & 15) << 3;
        int gr = row0 + r;
        float v[8];
        if (gr < nrows) {
            float4 a = *reinterpret_cast<const float4*>(X + (size_t)gr * D + kp);
            float4 b = *reinterpret_cast<const float4*>(X + (size_t)gr * D + kp + 4);
            v[0] = a.x; v[1] = a.y; v[2] = a.z; v[3] = a.w;
            v[4] = b.x; v[5] = b.y; v[6] = b.z; v[7] = b.w;
            if (mode == 1) {
#pragma unroll
                for (int i = 0; i < 8; i++) v[i] = v[i] * sPA[kp + i] + sPC[kp + i];
            }
        } else {
#pragma unroll
            for (int i = 0; i < 8; i++) v[i] = 0.f;
        }
        split_store8(v, Ah, Al, (uint32_t)(r * TILE_PITCH + kp * 2));
    }
    CP_WAIT1();       // W1 resident
    __syncthreads();

    const uint32_t uAh = smem_u32(Ah), uAl = smem_u32(Al);

    // ---- GEMM1 ----
    float acc[2][8][4];
#pragma unroll
    for (int i = 0; i < 2; i++)
#pragma unroll
        for (int j = 0; j < 8; j++) {
            int col = wn * 64 + j * 8 + 2 * tig;
            acc[i][j][0] = sB1[col]; acc[i][j][1] = sB1[col + 1];
            acc[i][j][2] = sB1[col]; acc[i][j][3] = sB1[col + 1];
        }
    warp_gemm3(uAh, uAl, smem_u32(W1h), smem_u32(W1l), lane, wm, wn, acc);
    __syncthreads();  // all warps done reading Ah/Al before rewrite

    // ---- epilogue1: h1 = elu(acc [+ P1[src]+P2[dst]]); re-split into A ----
#pragma unroll
    for (int i = 0; i < 2; i++) {
        int r0 = wm * 32 + i * 16 + g;
        int r1 = r0 + 8;
#pragma unroll
        for (int j = 0; j < 8; j++) {
            int col = wn * 64 + j * 8 + 2 * tig;
            float v0 = acc[i][j][0], v1 = acc[i][j][1];
            float v2 = acc[i][j][2], v3 = acc[i][j][3];
            if (GATHER) {
                const float2 p1a = *reinterpret_cast<const float2*>(g_P1 + (size_t)sSrc[r0] * D + col);
                const float2 p2a = *reinterpret_cast<const float2*>(g_P2 + (size_t)sDst[r0] * D + col);
                const float2 p1b = *reinterpret_cast<const float2*>(g_P1 + (size_t)sSrc[r1] * D + col);
                const float2 p2b = *reinterpret_cast<const float2*>(g_P2 + (size_t)sDst[r1] * D + col);
                v0 += p1a.x + p2a.x; v1 += p1a.y + p2a.y;
                v2 += p1b.x + p2b.x; v3 += p1b.y + p2b.y;
            }
            v0 = elu1(v0); v1 = elu1(v1); v2 = elu1(v2); v3 = elu1(v3);
            uint32_t hi, lo;
            split2t(v0, v1, hi, lo);
            *reinterpret_cast<uint32_t*>(Ah + r0 * TILE_PITCH + col * 2) = hi;
            *reinterpret_cast<uint32_t*>(Al + r0 * TILE_PITCH + col * 2) = lo;
            split2t(v2, v3, hi, lo);
            *reinterpret_cast<uint32_t*>(Ah + r1 * TILE_PITCH + col * 2) = hi;
            *reinterpret_cast<uint32_t*>(Al + r1 * TILE_PITCH + col * 2) = lo;
        }
    }
    CP_WAIT0();       // W2 resident
    __syncthreads();

    // ---- GEMM2 ----
#pragma unroll
    for (int i = 0; i < 2; i++)
#pragma unroll
        for (int j = 0; j < 8; j++) {
            int col = wn * 64 + j * 8 + 2 * tig;
            acc[i][j][0] = sB2[col]; acc[i][j][1] = sB2[col + 1];
            acc[i][j][2] = sB2[col]; acc[i][j][3] = sB2[col + 1];
        }
    warp_gemm3(uAh, uAl, smem_u32(W2h), smem_u32(W2l), lane, wm, wn, acc);

    // ---- epilogue2: h2 = elu(acc) -> gmem + smem scratch (stats) ----
    // scratch overlays W1h/W1l (GEMM2 reads only W2h/W2l/A tiles -> safe)
    float* scratch = reinterpret_cast<float*>(W1h);  // 128 x 132 fp32 = 67584 B
#pragma unroll
    for (int i = 0; i < 2; i++) {
        int r0 = wm * 32 + i * 16 + g;
        int r1 = r0 + 8;
        int gr0 = row0 + r0, gr1 = row0 + r1;
        bool va = gr0 < nrows, vb = gr1 < nrows;
#pragma unroll
        for (int j = 0; j < 8; j++) {
            int col = wn * 64 + j * 8 + 2 * tig;
            float v0 = va ? elu1(acc[i][j][0]) : 0.f;
            float v1 = va ? elu1(acc[i][j][1]) : 0.f;
            float v2 = vb ? elu1(acc[i][j][2]) : 0.f;
            float v3 = vb ? elu1(acc[i][j][3]) : 0.f;
            *reinterpret_cast<float2*>(scratch + r0 * 132 + col) = make_float2(v0, v1);
            *reinterpret_cast<float2*>(scratch + r1 * 132 + col) = make_float2(v2, v3);
            if (va) *reinterpret_cast<float2*>(out + (size_t)gr0 * D + col) = make_float2(v0, v1);
            if (vb) *reinterpret_cast<float2*>(out + (size_t)gr1 * D + col) = make_float2(v2, v3);
        }
    }
    __syncthreads();

    if (tid < 128) {
        float s = 0.f, q = 0.f;
#pragma unroll 4
        for (int r = 0; r < 128; r++) {
            float vv = scratch[r * 132 + tid];
            s += vv; q += vv * vv;
        }
        atomicAdd(&g_stats[stage * 256 + tid], s);
        atomicAdd(&g_stats[stage * 256 + 128 + tid], q);
    }
}

// ---------------- SIMT path for small node stages ----------------
__device__ __forceinline__ float2 ffma2(float2 d, float2 a, float2 b) {
    asm("fma.rn.f32x2 %0, %1, %2, %0;"
        : "+l"(reinterpret_cast<unsigned long long&>(d))
        : "l"(reinterpret_cast<unsigned long long&>(a)),
          "l"(reinterpret_cast<unsigned long long&>(b)));
    return d;
}

__device__ __forceinline__ void gemm_tile(const float* __restrict__ Xs,
                                          const float* __restrict__ Ws,
                                          float2 acc[8][4], int tx, int ty) {
#pragma unroll 2
    for (int k = 0; k < 128; k++) {
        float xv[8];
        float2 ww[4];
#pragma unroll
        for (int j = 0; j < 8; j++) xv[j] = Xs[(ty + 16 * j) * PADX + k];
#pragma unroll
        for (int p = 0; p < 4; p++) {
            float w0 = Ws[k * 128 + tx + 32 * p];
            float w1 = Ws[k * 128 + tx + 32 * p + 16];
            ww[p] = make_float2(w0, w1);
        }
#pragma unroll
        for (int j = 0; j < 8; j++) {
            float2 xx = make_float2(xv[j], xv[j]);
#pragma unroll
            for (int p = 0; p < 4; p++) acc[j][p] = ffma2(acc[j][p], xx, ww[p]);
        }
    }
}

__global__ void __launch_bounds__(256, 1)
mlp_kernel(const float* __restrict__ X,
           const float* __restrict__ W1, const float* __restrict__ B1,
           const float* __restrict__ W2, const float* __restrict__ B2,
           float* __restrict__ out, int nrows, int mode, int stage,
           const float* __restrict__ preA, const float* __restrict__ preC,
           const float* __restrict__ degp)
{
    extern __shared__ float smemf[];
    float* Xs = smemf;
    float* Ws = smemf + 128 * PADX;
    __shared__ float sB[128];
    __shared__ float sPA[128], sPC[128], sDeg[128];

    const int tid = threadIdx.x;
    const int tx = tid & 15, ty = tid >> 4;
    const int row0 = blockIdx.x * 128;

    if (tid < 128) {
        sB[tid] = B1[tid];
        if (mode == 1) { sPA[tid] = preA[tid]; sPC[tid] = preC[tid]; }
        if (mode == 2) {
            int r = row0 + tid;
            sDeg[tid] = (r < nrows) ? (1.f / fmaxf(degp[r], 1.f)) : 0.f;
        }
    }
    __syncthreads();

#pragma unroll
    for (int t = 0; t < 16; t++) {
        int idx = tid + t * 256;
        int r = idx >> 5;
        int c4 = (idx & 31) << 2;
        int gr = row0 + r;
        float4 v = make_float4(0.f, 0.f, 0.f, 0.f);
        if (gr < nrows) {
            v = *reinterpret_cast<const float4*>(X + (size_t)gr * D + c4);
            if (mode == 1) {
                v.x = v.x * sPA[c4] + sPC[c4];
                v.y = v.y * sPA[c4 + 1] + sPC[c4 + 1];
                v.z = v.z * sPA[c4 + 2] + sPC[c4 + 2];
                v.w = v.w * sPA[c4 + 3] + sPC[c4 + 3];
            } else if (mode == 2) {
                float s = sDeg[r];
                v.x *= s; v.y *= s; v.z *= s; v.w *= s;
            }
        }
        *reinterpret_cast<float4*>(Xs + r * PADX + c4) = v;
        reinterpret_cast<float4*>(Ws)[idx] = reinterpret_cast<const float4*>(W1)[idx];
    }
    __syncthreads();

    float2 acc[8][4];
#pragma unroll
    for (int j = 0; j < 8; j++)
#pragma unroll
        for (int p = 0; p < 4; p++)
            acc[j][p] = make_float2(sB[tx + 32 * p], sB[tx + 32 * p + 16]);

    gemm_tile(Xs, Ws, acc, tx, ty);
#pragma unroll
    for (int j = 0; j < 8; j++)
#pragma unroll
        for (int p = 0; p < 4; p++) {
            acc[j][p].x = elu1(acc[j][p].x);
            acc[j][p].y = elu1(acc[j][p].y);
        }
    __syncthreads();

#pragma unroll
    for (int j = 0; j < 8; j++) {
        int r = ty + 16 * j;
#pragma unroll
        for (int p = 0; p < 4; p++) {
            Xs[r * PADX + tx + 32 * p]      = acc[j][p].x;
            Xs[r * PADX + tx + 32 * p + 16] = acc[j][p].y;
        }
    }
#pragma unroll
    for (int t = 0; t < 16; t++) {
        int idx = tid + t * 256;
        reinterpret_cast<float4*>(Ws)[idx] = reinterpret_cast<const float4*>(W2)[idx];
    }
    if (tid < 128) sB[tid] = B2[tid];
    __syncthreads();

#pragma unroll
    for (int j = 0; j < 8; j++)
#pragma unroll
        for (int p = 0; p < 4; p++)
            acc[j][p] = make_float2(sB[tx + 32 * p], sB[tx + 32 * p + 16]);

    gemm_tile(Xs, Ws, acc, tx, ty);
#pragma unroll
    for (int j = 0; j < 8; j++)
#pragma unroll
        for (int p = 0; p < 4; p++) {
            acc[j][p].x = elu1(acc[j][p].x);
            acc[j][p].y = elu1(acc[j][p].y);
        }
    __syncthreads();

#pragma unroll
    for (int j = 0; j < 8; j++) {
        int r = ty + 16 * j;
        int gr = row0 + r;
        bool valid = gr < nrows;
#pragma unroll
        for (int p = 0; p < 4; p++) {
            int c0 = tx + 32 * p, c1 = c0 + 16;
            float vx = valid ? acc[j][p].x : 0.f;
            float vy = valid ? acc[j][p].y : 0.f;
            Xs[r * PADX + c0] = vx;
            Xs[r * PADX + c1] = vy;
            if (valid) {
                out[(size_t)gr * D + c0] = vx;
                out[(size_t)gr * D + c1] = vy;
            }
        }
    }
    __syncthreads();

    if (tid < 128) {
        float s = 0.f, q = 0.f;
#pragma unroll 4
        for (int r = 0; r < 128; r++) {
            float vv = Xs[r * PADX + tid];
            s += vv; q += vv * vv;
        }
        atomicAdd(&g_stats[stage * 256 + tid], s);
        atomicAdd(&g_stats[stage * 256 + 128 + tid], q);
    }
}

__global__ void finalize_bn(int stage, float cnt,
                            const float* __restrict__ g, const float* __restrict__ bt)
{
    int j = threadIdx.x;
    float s1 = g_stats[stage * 256 + j];
    float s2 = g_stats[stage * 256 + 128 + j];
    float mu = s1 / cnt;
    float var = s2 / cnt - mu * mu;
    float a = g[j] * rsqrtf(var + EPS);
    g_bnA[stage * 128 + j] = a;
    g_bnC[stage * 128 + j] = bt[j] - mu * a;
}

__global__ void __launch_bounds__(256)
scatter_kernel(const int* __restrict__ dst, int nedges)
{
    int lane = threadIdx.x & 31;
    int warp = (blockIdx.x * 256 + threadIdx.x) >> 5;
    int nw = (gridDim.x * 256) >> 5;
    float4 A0 = reinterpret_cast<const float4*>(g_bnA)[lane];
    float4 C0 = reinterpret_cast<const float4*>(g_bnC)[lane];
    float4 A1 = reinterpret_cast<const float4*>(g_bnA + 128)[lane];
    float4 C1 = reinterpret_cast<const float4*>(g_bnC + 128)[lane];
    for (int e = warp; e < nedges; e += nw) {
        int d = __ldg(dst + e);
        float4 t = reinterpret_cast<const float4*>(g_t1 + (size_t)e * D)[lane];
        float4 u = reinterpret_cast<const float4*>(g_u + (size_t)e * D)[lane];
        float4 h;
        h.x = (t.x * A0.x + C0.x) + (u.x * A1.x + C1.x);
        h.y = (t.y * A0.y + C0.y) + (u.y * A1.y + C1.y);
        h.z = (t.z * A0.z + C0.z) + (u.z * A1.z + C1.z);
        h.w = (t.w * A0.w + C0.w) + (u.w * A1.w + C1.w);
        float* base = g_agg + (size_t)d * D + lane * 4;
        atomicAdd(base + 0, h.x);
        atomicAdd(base + 1, h.y);
        atomicAdd(base + 2, h.z);
        atomicAdd(base + 3, h.w);
        if (lane == 0) atomicAdd(&g_deg[d], 1.f);
    }
}

__global__ void __launch_bounds__(256, 1)
node_final_kernel(const float* __restrict__ eW1, int nrows)
{
    extern __shared__ float smemf[];
    float* Hs = smemf;
    float* Ws = smemf + 128 * PADX;
    const int tid = threadIdx.x;
    const int tx = tid & 15, ty = tid >> 4;
    const int row0 = blockIdx.x * 128;

#pragma unroll
    for (int t = 0; t < 16; t++) {
        int idx = tid + t * 256;
        int r = idx >> 5;
        int c4 = (idx & 31) << 2;
        int gr = row0 + r;
        float4 h = make_float4(0.f, 0.f, 0.f, 0.f);
        if (gr < nrows) {
            float4 v = *reinterpret_cast<const float4*>(g_v + (size_t)gr * D + c4);
            float4 w = *reinterpret_cast<const float4*>(g_w + (size_t)gr * D + c4);
            float4 A2 = reinterpret_cast<const float4*>(g_bnA + 256)[c4 >> 2];
            float4 C2 = reinterpret_cast<const float4*>(g_bnC + 256)[c4 >> 2];
            float4 A3 = reinterpret_cast<const float4*>(g_bnA + 384)[c4 >> 2];
            float4 C3 = reinterpret_cast<const float4*>(g_bnC + 384)[c4 >> 2];
            h.x = (w.x * A3.x + C3.x) + (v.x * A2.x + C2.x);
            h.y = (w.y * A3.y + C3.y) + (v.y * A2.y + C2.y);
            h.z = (w.z * A3.z + C3.z) + (v.z * A2.z + C2.z);
            h.w = (w.w * A3.w + C3.w) + (v.w * A2.w + C2.w);
        }
        *reinterpret_cast<float4*>(Hs + r * PADX + c4) = h;
        reinterpret_cast<float4*>(Ws)[idx] =
            reinterpret_cast<const float4*>(eW1 + 128 * 128)[idx];
    }
    __syncthreads();

    float2 acc[8][4];
#pragma unroll
    for (int j = 0; j < 8; j++)
#pragma unroll
        for (int p = 0; p < 4; p++) acc[j][p] = make_float2(0.f, 0.f);
    gemm_tile(Hs, Ws, acc, tx, ty);
    __syncthreads();

#pragma unroll
    for (int j = 0; j < 8; j++) {
        int gr = row0 + ty + 16 * j;
        if (gr < nrows)
#pragma unroll
            for (int p = 0; p < 4; p++) {
                g_P1[(size_t)gr * D + tx + 32 * p]      = acc[j][p].x;
                g_P1[(size_t)gr * D + tx + 32 * p + 16] = acc[j][p].y;
            }
    }
#pragma unroll
    for (int t = 0; t < 16; t++) {
        int idx = tid + t * 256;
        reinterpret_cast<float4*>(Ws)[idx] =
            reinterpret_cast<const float4*>(eW1 + 256 * 128)[idx];
    }
    __syncthreads();

#pragma unroll
    for (int j = 0; j < 8; j++)
#pragma unroll
        for (int p = 0; p < 4; p++) acc[j][p] = make_float2(0.f, 0.f);
    gemm_tile(Hs, Ws, acc, tx, ty);

#pragma unroll
    for (int j = 0; j < 8; j++) {
        int gr = row0 + ty + 16 * j;
        if (gr < nrows)
#pragma unroll
            for (int p = 0; p < 4; p++) {
                g_P2[(size_t)gr * D + tx + 32 * p]      = acc[j][p].x;
                g_P2[(size_t)gr * D + tx + 32 * p + 16] = acc[j][p].y;
            }
    }
}

__global__ void norm_out_kernel(float* __restrict__ out, int n4)
{
    int idx = blockIdx.x * blockDim.x + threadIdx.x;
    if (idx >= n4) return;
    int cv = idx & 31;
    float4 A = reinterpret_cast<const float4*>(g_bnA + 512)[cv];
    float4 C = reinterpret_cast<const float4*>(g_bnC + 512)[cv];
    float4 v = reinterpret_cast<float4*>(out)[idx];
    v.x = v.x * A.x + C.x;
    v.y = v.y * A.y + C.y;
    v.z = v.z * A.z + C.z;
    v.w = v.w * A.w + C.w;
    reinterpret_cast<float4*>(out)[idx] = v;
}

// ---------------- host orchestration ----------------
extern "C" void kernel_launch(void* const* d_in, const int* in_sizes, int n_in,
                              void* d_out, int out_size)
{
    if (n_in < 15) return;
    const float* edata = (const float*)d_in[0];
    const int*   src   = (const int*)d_in[1];
    const int*   dst   = (const int*)d_in[2];
    int w = (n_in >= 16) ? 4 : 3;
    const float* W1s = (const float*)d_in[w + 0];
    const float* b1s = (const float*)d_in[w + 1];
    const float* W2s = (const float*)d_in[w + 2];
    const float* b2s = (const float*)d_in[w + 3];
    const float* gs  = (const float*)d_in[w + 4];
    const float* bts = (const float*)d_in[w + 5];
    const float* eW1 = (const float*)d_in[w + 6];
    const float* eb1 = (const float*)d_in[w + 7];
    const float* eW2 = (const float*)d_in[w + 8];
    const float* eb2 = (const float*)d_in[w + 9];
    const float* eg  = (const float*)d_in[w + 10];
    const float* ebt = (const float*)d_in[w + 11];

    int E = in_sizes[0] / D;
    int N = 20000;

    float *p_t1, *p_u, *p_v, *p_w2, *p_agg, *p_deg, *p_stats, *p_bnA, *p_bnC;
    cudaGetSymbolAddress((void**)&p_t1, g_t1);
    cudaGetSymbolAddress((void**)&p_u, g_u);
    cudaGetSymbolAddress((void**)&p_v, g_v);
    cudaGetSymbolAddress((void**)&p_w2, g_w);
    cudaGetSymbolAddress((void**)&p_agg, g_agg);
    cudaGetSymbolAddress((void**)&p_deg, g_deg);
    cudaGetSymbolAddress((void**)&p_stats, g_stats);
    cudaGetSymbolAddress((void**)&p_bnA, g_bnA);
    cudaGetSymbolAddress((void**)&p_bnC, g_bnC);

    cudaFuncSetAttribute(mlp_kernel, cudaFuncAttributeMaxDynamicSharedMemorySize, SMEM_BYTES);
    cudaFuncSetAttribute(node_final_kernel, cudaFuncAttributeMaxDynamicSharedMemorySize, SMEM_BYTES);
    cudaFuncSetAttribute(tc_mlp_tpl<false>, cudaFuncAttributeMaxDynamicSharedMemorySize, TC_SMEM);
    cudaFuncSetAttribute(tc_mlp_tpl<true>,  cudaFuncAttributeMaxDynamicSharedMemorySize, TC_SMEM);

    cudaMemsetAsync(p_stats, 0, 5 * 2 * 128 * sizeof(float), 0);
    cudaMemsetAsync(p_agg, 0, (size_t)NODE_CAP * D * sizeof(float), 0);
    cudaMemsetAsync(p_deg, 0, NODE_CAP * sizeof(float), 0);

    int egrid = (E + 127) / 128;
    int ngrid = (N + 127) / 128;

    // weight prep: transpose + bf16 hi/lo split
    prep_weights<<<(6 * 16384 + 255) / 256, 256>>>(W1s, W2s, eW1, eW2);

    // edge MLP0 (tensor cores)
    tc_mlp_tpl<false><<<egrid, 256, TC_SMEM>>>(edata, 0, 1, b1s, b2s,
                                               p_t1, E, 0, 0, nullptr, nullptr,
                                               nullptr, nullptr);
    finalize_bn<<<1, 128>>>(0, (float)E, gs, bts);
    // edge MLP1 (input = BN0(t1), folded affine)
    tc_mlp_tpl<false><<<egrid, 256, TC_SMEM>>>(p_t1, 2, 3, b1s + 128, b2s + 128,
                                               p_u, E, 1, 1, p_bnA, p_bnC,
                                               nullptr, nullptr);
    finalize_bn<<<1, 128>>>(1, (float)E, gs + 128, bts + 128);
    // h_e = BN0(t1)+BN1(u); scatter-sum + degree
    scatter_kernel<<<2048, 256>>>(dst, E);
    // node MLP2 (input = agg / max(deg,1)) — SIMT
    mlp_kernel<<<ngrid, 256, SMEM_BYTES>>>(p_agg, W1s + 2 * 16384, b1s + 256,
                                           W2s + 2 * 16384, b2s + 256,
                                           p_v, N, 2, 2, nullptr, nullptr, p_deg);
    finalize_bn<<<1, 128>>>(2, (float)N, gs + 256, bts + 256);
    // node MLP3 — SIMT
    mlp_kernel<<<ngrid, 256, SMEM_BYTES>>>(p_v, W1s + 3 * 16384, b1s + 384,
                                           W2s + 3 * 16384, b2s + 384,
                                           p_w2, N, 1, 3, p_bnA + 256, p_bnC + 256, nullptr);
    finalize_bn<<<1, 128>>>(3, (float)N, gs + 384, bts + 384);
    // h_n + per-node partials P1/P2 through eW1 src/dst slices — SIMT
    node_final_kernel<<<ngrid, 256, SMEM_BYTES>>>(eW1, N);
    // final edge MLP (tensor cores, with gathers) -> d_out (pre-BN)
    tc_mlp_tpl<true><<<egrid, 256, TC_SMEM>>>(edata, 4, 5, eb1, eb2,
                                              (float*)d_out, E, 0, 4, nullptr, nullptr,
                                              src, dst);
    finalize_bn<<<1, 128>>>(4, (float)E, eg, ebt);
    int n4 = E * (D / 4);
    norm_out_kernel<<<(n4 + 255) / 256, 256>>>((float*)d_out, n4);
}

// round 6
// speedup vs baseline: 1.9537x; 1.0519x over previous
#include <cuda_runtime.h>
#include <cuda_bf16.h>
#include <math.h>
#include <stdint.h>

#define D 128
#define EPS 1e-5f
#define PADX 132
#define NODE_CAP 20096
#define E_MAX 640000

static const int SMEM_BYTES = (128 * PADX + 128 * 128) * 4;  // SIMT kernels
// TC kernel smem: 6 tiles (Ah, Al, W1h, W1l, W2h, W2l), 128 rows x 272 bytes
#define TILE_PITCH 272
#define TILE_BYTES_PAD (128 * TILE_PITCH)  // 34816
static const int TC_SMEM = 6 * TILE_BYTES_PAD;  // 208896

// ---------------- scratch ----------------
__device__ float g_t1[(size_t)E_MAX * D];
__device__ float g_u [(size_t)E_MAX * D];
__device__ float g_v [(size_t)NODE_CAP * D];
__device__ float g_w [(size_t)NODE_CAP * D];
__device__ float g_P1[(size_t)NODE_CAP * D];
__device__ float g_P2[(size_t)NODE_CAP * D];
__device__ float g_agg[(size_t)NODE_CAP * D];
__device__ float g_deg[NODE_CAP];
__device__ float g_stats[5 * 2 * 128];
__device__ float g_bnA[5 * 128];
__device__ float g_bnC[5 * 128];
// prepped weights: 6 matrices x (hi,lo), each [n][k] bf16 128x128 = 32KB
__device__ __align__(256) unsigned char g_wprep[12 * 32768];

// ---------------- helpers ----------------
// fast ELU: exp(x)-1 via ex2.approx (abs err ~2^-22, fine for 1e-3 budget)
__device__ __forceinline__ float elu1(float x) {
    float e;
    asm("ex2.approx.f32 %0, %1;" : "=f"(e) : "f"(x * 1.4426950408889634f));
    return x > 0.f ? x : (e - 1.0f);
}

__device__ __forceinline__ uint32_t smem_u32(const void* p) {
    uint32_t a;
    asm("{ .reg .u64 t; cvta.to.shared.u64 t, %1; cvt.u32.u64 %0, t; }" : "=r"(a) : "l"(p));
    return a;
}

#define CP_ASYNC16(dst, src) \
    asm volatile("cp.async.cg.shared.global [%0], [%1], 16;" :: "r"(dst), "l"(src))
#define CP_COMMIT() asm volatile("cp.async.commit_group;")
#define CP_WAIT1()  asm volatile("cp.async.wait_group 1;")
#define CP_WAIT0()  asm volatile("cp.async.wait_group 0;")

// truncation split: hi = a with low 16 bits zeroed (exact bf16), lo = bf16(a - hi)
__device__ __forceinline__ void split2t(float a, float b, uint32_t& hi, uint32_t& lo) {
    uint32_t ai = __float_as_uint(a), bi = __float_as_uint(b);
    hi = __byte_perm(ai, bi, 0x7632);  // {a.hi16 in low, b.hi16 in high}
    float la = a - __uint_as_float(ai & 0xFFFF0000u);
    float lb = b - __uint_as_float(bi & 0xFFFF0000u);
    asm("cvt.rn.bf16x2.f32 %0, %1, %2;" : "=r"(lo) : "f"(lb), "f"(la));
}

// split 8 fp32 -> bf16 hi/lo, 16B stores to padded tiles
__device__ __forceinline__ void split_store8(const float* v, unsigned char* Ah,
                                             unsigned char* Al, uint32_t off) {
    uint32_t hw[4], lw[4];
#pragma unroll
    for (int i = 0; i < 4; i++) split2t(v[2 * i], v[2 * i + 1], hw[i], lw[i]);
    *reinterpret_cast<uint4*>(Ah + off) = make_uint4(hw[0], hw[1], hw[2], hw[3]);
    *reinterpret_cast<uint4*>(Al + off) = make_uint4(lw[0], lw[1], lw[2], lw[3]);
}

__device__ __forceinline__ void ldm4(uint32_t* r, uint32_t a) {
    asm volatile("ldmatrix.sync.aligned.m8n8.x4.shared.b16 {%0,%1,%2,%3}, [%4];"
                 : "=r"(r[0]), "=r"(r[1]), "=r"(r[2]), "=r"(r[3]) : "r"(a));
}

__device__ __forceinline__ void mma16816(float* c, const uint32_t* a, const uint32_t* b) {
    asm volatile(
        "mma.sync.aligned.m16n8k16.row.col.f32.bf16.bf16.f32 "
        "{%0,%1,%2,%3}, {%4,%5,%6,%7}, {%8,%9}, {%0,%1,%2,%3};"
        : "+f"(c[0]), "+f"(c[1]), "+f"(c[2]), "+f"(c[3])
        : "r"(a[0]), "r"(a[1]), "r"(a[2]), "r"(a[3]), "r"(b[0]), "r"(b[1]));
}

// fused 3-split warp GEMM, k-outer: per k-step load Ah/Al/Wh/Wl fragments ONCE,
// then acc += Ah@Wh + Al@Wh + Ah@Wl.  (warp tile m32 x n64)
__device__ __forceinline__ void warp_gemm3(uint32_t Ah, uint32_t Al,
                                           uint32_t Wh, uint32_t Wl,
                                           int lane, int wm, int wn,
                                           float acc[2][8][4]) {
    const int arow = lane & 15;
    const int kA = ((lane >> 4) << 3) * 2;               // byte k-offset
    const int brow = ((lane >> 4) << 3) + (lane & 7);
    const int kB = (((lane >> 3) & 1) << 3) * 2;
    const uint32_t aoff0 = (uint32_t)((wm * 32 + arow) * TILE_PITCH) + kA;
    const uint32_t aoff1 = aoff0 + 16 * TILE_PITCH;
    uint32_t boff[4];
#pragma unroll
    for (int p = 0; p < 4; p++)
        boff[p] = (uint32_t)((wn * 64 + p * 16 + brow) * TILE_PITCH) + kB;

#pragma unroll
    for (int k0 = 0; k0 < 128; k0 += 16) {
        uint32_t ah0[4], ah1[4], al0[4], al1[4], bh[4][4], bl[4][4];
        ldm4(ah0, Ah + aoff0 + k0 * 2);
        ldm4(ah1, Ah + aoff1 + k0 * 2);
        ldm4(al0, Al + aoff0 + k0 * 2);
        ldm4(al1, Al + aoff1 + k0 * 2);
#pragma unroll
        for (int p = 0; p < 4; p++) ldm4(bh[p], Wh + boff[p] + k0 * 2);
#pragma unroll
        for (int p = 0; p < 4; p++) ldm4(bl[p], Wl + boff[p] + k0 * 2);
#pragma unroll
        for (int j = 0; j < 8; j++) {
            const uint32_t* bhj = &bh[j >> 1][(j & 1) * 2];
            mma16816(acc[0][j], ah0, bhj);
            mma16816(acc[1][j], ah1, bhj);
        }
#pragma unroll
        for (int j = 0; j < 8; j++) {
            const uint32_t* bhj = &bh[j >> 1][(j & 1) * 2];
            mma16816(acc[0][j], al0, bhj);
            mma16816(acc[1][j], al1, bhj);
        }
#pragma unroll
        for (int j = 0; j < 8; j++) {
            const uint32_t* blj = &bl[j >> 1][(j & 1) * 2];
            mma16816(acc[0][j], ah0, blj);
            mma16816(acc[1][j], ah1, blj);
        }
    }
}

// ---------------- weight prep: transpose + bf16 split ----------------
// m: 0:W1s[0] 1:W2s[0] 2:W1s[1] 3:W2s[1] 4:eW1[0:128,:] 5:eW2
__global__ void prep_weights(const float* __restrict__ W1s, const float* __restrict__ W2s,
                             const float* __restrict__ eW1, const float* __restrict__ eW2)
{
    int idx = blockIdx.x * 256 + threadIdx.x;
    if (idx >= 6 * 16384) return;
    int m = idx >> 14;
    int e = idx & 16383;
    int n = e >> 7, k = e & 127;
    const float* W;
    switch (m) {
        case 0: W = W1s; break;
        case 1: W = W2s; break;
        case 2: W = W1s + 16384; break;
        case 3: W = W2s + 16384; break;
        case 4: W = eW1; break;
        default: W = eW2; break;
    }
    float v = W[k * 128 + n];
    __nv_bfloat16 h = __float2bfloat16(v);
    __nv_bfloat16 l = __float2bfloat16(v - __bfloat162float(h));
    *reinterpret_cast<__nv_bfloat16*>(g_wprep + (size_t)(2 * m) * 32768 + (size_t)e * 2) = h;
    *reinterpret_cast<__nv_bfloat16*>(g_wprep + (size_t)(2 * m + 1) * 32768 + (size_t)e * 2) = l;
}

// ---------------- tensor-core fused MLP over 128-row tiles ----------------
template <bool GATHER>
__global__ void __launch_bounds__(256, 1)
tc_mlp_tpl(const float* __restrict__ X, int m1, int m2,
           const float* __restrict__ B1, const float* __restrict__ B2,
           float* __restrict__ out, int nrows, int mode, int stage,
           const float* __restrict__ preA, const float* __restrict__ preC,
           const int* __restrict__ srcI, const int* __restrict__ dstI)
{
    extern __shared__ unsigned char smem[];
    unsigned char* Ah  = smem;
    unsigned char* Al  = smem + TILE_BYTES_PAD;
    unsigned char* W1h = smem + 2 * TILE_BYTES_PAD;
    unsigned char* W1l = smem + 3 * TILE_BYTES_PAD;
    unsigned char* W2h = smem + 4 * TILE_BYTES_PAD;
    unsigned char* W2l = smem + 5 * TILE_BYTES_PAD;
    __shared__ float sB1[128], sB2[128], sPA[128], sPC[128];
    __shared__ int sSrc[128], sDst[128];

    const int tid = threadIdx.x, wid = tid >> 5, lane = tid & 31;
    const int wm = wid & 3, wn = wid >> 2;       // warp tile: rows 32*wm, cols 64*wn
    const int g = lane >> 2, tig = lane & 3;
    const int row0 = blockIdx.x * 128;

    // ---- async W1 prefetch (group old), W2 prefetch (group young) ----
    {
        const char* g1 = (const char*)(g_wprep + (size_t)(2 * m1) * 32768);
        const char* g2 = (const char*)(g_wprep + (size_t)(2 * m2) * 32768);
#pragma unroll
        for (int t = 0; t < 8; t++) {
            int idx = tid + 256 * t;
            uint32_t off = (uint32_t)((idx >> 4) * TILE_PITCH + (idx & 15) * 16);
            CP_ASYNC16(smem_u32(W1h + off), g1 + (size_t)idx * 16);
            CP_ASYNC16(smem_u32(W1l + off), g1 + 32768 + (size_t)idx * 16);
        }
        CP_COMMIT();
#pragma unroll
        for (int t = 0; t < 8; t++) {
            int idx = tid + 256 * t;
            uint32_t off = (uint32_t)((idx >> 4) * TILE_PITCH + (idx & 15) * 16);
            CP_ASYNC16(smem_u32(W2h + off), g2 + (size_t)idx * 16);
            CP_ASYNC16(smem_u32(W2l + off), g2 + 32768 + (size_t)idx * 16);
        }
        CP_COMMIT();
    }

    if (tid < 128) {
        sB1[tid] = B1[tid];
        sB2[tid] = B2[tid];
        if (mode == 1) { sPA[tid] = preA[tid]; sPC[tid] = preC[tid]; }
        if (GATHER) {
            int gr = row0 + tid;
            sSrc[tid] = (gr < nrows) ? srcI[gr] : 0;
            sDst[tid] = (gr < nrows) ? dstI[gr] : 0;
        }
    }
    __syncthreads();  // sPA/sPC visible before A-load uses them

    // ---- coalesced load + split A tile (8-float groups, lane-contiguous) ----
#pragma unroll
    for (int t = 0; t < 8; t++) {
        int q = tid + 256 * t;        // 2048 groups of 8 floats
        int r = q >> 4;
        int kp = (q & 15) << 3;
        int gr = row0 + r;
        float v[8];
        if (gr < nrows) {
            float4 a = *reinterpret_cast<const float4*>(X + (size_t)gr * D + kp);
            float4 b = *reinterpret_cast<const float4*>(X + (size_t)gr * D + kp + 4);
            v[0] = a.x; v[1] = a.y; v[2] = a.z; v[3] = a.w;
            v[4] = b.x; v[5] = b.y; v[6] = b.z; v[7] = b.w;
            if (mode == 1) {
#pragma unroll
                for (int i = 0; i < 8; i++) v[i] = v[i] * sPA[kp + i] + sPC[kp + i];
            }
        } else {
#pragma unroll
            for (int i = 0; i < 8; i++) v[i] = 0.f;
        }
        split_store8(v, Ah, Al, (uint32_t)(r * TILE_PITCH + kp * 2));
    }
    CP_WAIT1();       // W1 resident
    __syncthreads();

    const uint32_t uAh = smem_u32(Ah), uAl = smem_u32(Al);

    // ---- GEMM1 ----
    float acc[2][8][4];
#pragma unroll
    for (int i = 0; i < 2; i++)
#pragma unroll
        for (int j = 0; j < 8; j++) {
            int col = wn * 64 + j * 8 + 2 * tig;
            acc[i][j][0] = sB1[col]; acc[i][j][1] = sB1[col + 1];
            acc[i][j][2] = sB1[col]; acc[i][j][3] = sB1[col + 1];
        }
    warp_gemm3(uAh, uAl, smem_u32(W1h), smem_u32(W1l), lane, wm, wn, acc);
    __syncthreads();  // all warps done reading Ah/Al before rewrite

    // ---- epilogue1: h1 = elu(acc [+ P1[src]+P2[dst]]); re-split into A ----
#pragma unroll
    for (int i = 0; i < 2; i++) {
        int r0 = wm * 32 + i * 16 + g;
        int r1 = r0 + 8;
#pragma unroll
        for (int j = 0; j < 8; j++) {
            int col = wn * 64 + j * 8 + 2 * tig;
            float v0 = acc[i][j][0], v1 = acc[i][j][1];
            float v2 = acc[i][j][2], v3 = acc[i][j][3];
            if (GATHER) {
                const float2 p1a = *reinterpret_cast<const float2*>(g_P1 + (size_t)sSrc[r0] * D + col);
                const float2 p2a = *reinterpret_cast<const float2*>(g_P2 + (size_t)sDst[r0] * D + col);
                const float2 p1b = *reinterpret_cast<const float2*>(g_P1 + (size_t)sSrc[r1] * D + col);
                const float2 p2b = *reinterpret_cast<const float2*>(g_P2 + (size_t)sDst[r1] * D + col);
                v0 += p1a.x + p2a.x; v1 += p1a.y + p2a.y;
                v2 += p1b.x + p2b.x; v3 += p1b.y + p2b.y;
            }
            v0 = elu1(v0); v1 = elu1(v1); v2 = elu1(v2); v3 = elu1(v3);
            uint32_t hi, lo;
            split2t(v0, v1, hi, lo);
            *reinterpret_cast<uint32_t*>(Ah + r0 * TILE_PITCH + col * 2) = hi;
            *reinterpret_cast<uint32_t*>(Al + r0 * TILE_PITCH + col * 2) = lo;
            split2t(v2, v3, hi, lo);
            *reinterpret_cast<uint32_t*>(Ah + r1 * TILE_PITCH + col * 2) = hi;
            *reinterpret_cast<uint32_t*>(Al + r1 * TILE_PITCH + col * 2) = lo;
        }
    }
    CP_WAIT0();       // W2 resident
    __syncthreads();

    // ---- GEMM2 ----
#pragma unroll
    for (int i = 0; i < 2; i++)
#pragma unroll
        for (int j = 0; j < 8; j++) {
            int col = wn * 64 + j * 8 + 2 * tig;
            acc[i][j][0] = sB2[col]; acc[i][j][1] = sB2[col + 1];
            acc[i][j][2] = sB2[col]; acc[i][j][3] = sB2[col + 1];
        }
    warp_gemm3(uAh, uAl, smem_u32(W2h), smem_u32(W2l), lane, wm, wn, acc);

    // ---- epilogue2: h2 = elu(acc) -> gmem + smem scratch (stats) ----
    // scratch overlays W1h/W1l (GEMM2 reads only W2h/W2l/A tiles -> safe)
    float* scratch = reinterpret_cast<float*>(W1h);  // 128 x 132 fp32 = 67584 B
#pragma unroll
    for (int i = 0; i < 2; i++) {
        int r0 = wm * 32 + i * 16 + g;
        int r1 = r0 + 8;
        int gr0 = row0 + r0, gr1 = row0 + r1;
        bool va = gr0 < nrows, vb = gr1 < nrows;
#pragma unroll
        for (int j = 0; j < 8; j++) {
            int col = wn * 64 + j * 8 + 2 * tig;
            float v0 = va ? elu1(acc[i][j][0]) : 0.f;
            float v1 = va ? elu1(acc[i][j][1]) : 0.f;
            float v2 = vb ? elu1(acc[i][j][2]) : 0.f;
            float v3 = vb ? elu1(acc[i][j][3]) : 0.f;
            *reinterpret_cast<float2*>(scratch + r0 * 132 + col) = make_float2(v0, v1);
            *reinterpret_cast<float2*>(scratch + r1 * 132 + col) = make_float2(v2, v3);
            if (va) *reinterpret_cast<float2*>(out + (size_t)gr0 * D + col) = make_float2(v0, v1);
            if (vb) *reinterpret_cast<float2*>(out + (size_t)gr1 * D + col) = make_float2(v2, v3);
        }
    }
    __syncthreads();

    if (tid < 128) {
        float s = 0.f, q = 0.f;
#pragma unroll 4
        for (int r = 0; r < 128; r++) {
            float vv = scratch[r * 132 + tid];
            s += vv; q += vv * vv;
        }
        atomicAdd(&g_stats[stage * 256 + tid], s);
        atomicAdd(&g_stats[stage * 256 + 128 + tid], q);
    }
}

// ---------------- SIMT path for small node stages ----------------
__device__ __forceinline__ float2 ffma2(float2 d, float2 a, float2 b) {
    asm("fma.rn.f32x2 %0, %1, %2, %0;"
        : "+l"(reinterpret_cast<unsigned long long&>(d))
        : "l"(reinterpret_cast<unsigned long long&>(a)),
          "l"(reinterpret_cast<unsigned long long&>(b)));
    return d;
}

__device__ __forceinline__ void gemm_tile(const float* __restrict__ Xs,
                                          const float* __restrict__ Ws,
                                          float2 acc[8][4], int tx, int ty) {
#pragma unroll 2
    for (int k = 0; k < 128; k++) {
        float xv[8];
        float2 ww[4];
#pragma unroll
        for (int j = 0; j < 8; j++) xv[j] = Xs[(ty + 16 * j) * PADX + k];
#pragma unroll
        for (int p = 0; p < 4; p++) {
            float w0 = Ws[k * 128 + tx + 32 * p];
            float w1 = Ws[k * 128 + tx + 32 * p + 16];
            ww[p] = make_float2(w0, w1);
        }
#pragma unroll
        for (int j = 0; j < 8; j++) {
            float2 xx = make_float2(xv[j], xv[j]);
#pragma unroll
            for (int p = 0; p < 4; p++) acc[j][p] = ffma2(acc[j][p], xx, ww[p]);
        }
    }
}

__global__ void __launch_bounds__(256, 1)
mlp_kernel(const float* __restrict__ X,
           const float* __restrict__ W1, const float* __restrict__ B1,
           const float* __restrict__ W2, const float* __restrict__ B2,
           float* __restrict__ out, int nrows, int mode, int stage,
           const float* __restrict__ preA, const float* __restrict__ preC,
           const float* __restrict__ degp)
{
    extern __shared__ float smemf[];
    float* Xs = smemf;
    float* Ws = smemf + 128 * PADX;
    __shared__ float sB[128];
    __shared__ float sPA[128], sPC[128], sDeg[128];

    const int tid = threadIdx.x;
    const int tx = tid & 15, ty = tid >> 4;
    const int row0 = blockIdx.x * 128;

    if (tid < 128) {
        sB[tid] = B1[tid];
        if (mode == 1) { sPA[tid] = preA[tid]; sPC[tid] = preC[tid]; }
        if (mode == 2) {
            int r = row0 + tid;
            sDeg[tid] = (r < nrows) ? (1.f / fmaxf(degp[r], 1.f)) : 0.f;
        }
    }
    __syncthreads();

#pragma unroll
    for (int t = 0; t < 16; t++) {
        int idx = tid + t * 256;
        int r = idx >> 5;
        int c4 = (idx & 31) << 2;
        int gr = row0 + r;
        float4 v = make_float4(0.f, 0.f, 0.f, 0.f);
        if (gr < nrows) {
            v = *reinterpret_cast<const float4*>(X + (size_t)gr * D + c4);
            if (mode == 1) {
                v.x = v.x * sPA[c4] + sPC[c4];
                v.y = v.y * sPA[c4 + 1] + sPC[c4 + 1];
                v.z = v.z * sPA[c4 + 2] + sPC[c4 + 2];
                v.w = v.w * sPA[c4 + 3] + sPC[c4 + 3];
            } else if (mode == 2) {
                float s = sDeg[r];
                v.x *= s; v.y *= s; v.z *= s; v.w *= s;
            }
        }
        *reinterpret_cast<float4*>(Xs + r * PADX + c4) = v;
        reinterpret_cast<float4*>(Ws)[idx] = reinterpret_cast<const float4*>(W1)[idx];
    }
    __syncthreads();

    float2 acc[8][4];
#pragma unroll
    for (int j = 0; j < 8; j++)
#pragma unroll
        for (int p = 0; p < 4; p++)
            acc[j][p] = make_float2(sB[tx + 32 * p], sB[tx + 32 * p + 16]);

    gemm_tile(Xs, Ws, acc, tx, ty);
#pragma unroll
    for (int j = 0; j < 8; j++)
#pragma unroll
        for (int p = 0; p < 4; p++) {
            acc[j][p].x = elu1(acc[j][p].x);
            acc[j][p].y = elu1(acc[j][p].y);
        }
    __syncthreads();

#pragma unroll
    for (int j = 0; j < 8; j++) {
        int r = ty + 16 * j;
#pragma unroll
        for (int p = 0; p < 4; p++) {
            Xs[r * PADX + tx + 32 * p]      = acc[j][p].x;
            Xs[r * PADX + tx + 32 * p + 16] = acc[j][p].y;
        }
    }
#pragma unroll
    for (int t = 0; t < 16; t++) {
        int idx = tid + t * 256;
        reinterpret_cast<float4*>(Ws)[idx] = reinterpret_cast<const float4*>(W2)[idx];
    }
    if (tid < 128) sB[tid] = B2[tid];
    __syncthreads();

#pragma unroll
    for (int j = 0; j < 8; j++)
#pragma unroll
        for (int p = 0; p < 4; p++)
            acc[j][p] = make_float2(sB[tx + 32 * p], sB[tx + 32 * p + 16]);

    gemm_tile(Xs, Ws, acc, tx, ty);
#pragma unroll
    for (int j = 0; j < 8; j++)
#pragma unroll
        for (int p = 0; p < 4; p++) {
            acc[j][p].x = elu1(acc[j][p].x);
            acc[j][p].y = elu1(acc[j][p].y);
        }
    __syncthreads();

#pragma unroll
    for (int j = 0; j < 8; j++) {
        int r = ty + 16 * j;
        int gr = row0 + r;
        bool valid = gr < nrows;
#pragma unroll
        for (int p = 0; p < 4; p++) {
            int c0 = tx + 32 * p, c1 = c0 + 16;
            float vx = valid ? acc[j][p].x : 0.f;
            float vy = valid ? acc[j][p].y : 0.f;
            Xs[r * PADX + c0] = vx;
            Xs[r * PADX + c1] = vy;
            if (valid) {
                out[(size_t)gr * D + c0] = vx;
                out[(size_t)gr * D + c1] = vy;
            }
        }
    }
    __syncthreads();

    if (tid < 128) {
        float s = 0.f, q = 0.f;
#pragma unroll 4
        for (int r = 0; r < 128; r++) {
            float vv = Xs[r * PADX + tid];
            s += vv; q += vv * vv;
        }
        atomicAdd(&g_stats[stage * 256 + tid], s);
        atomicAdd(&g_stats[stage * 256 + 128 + tid], q);
    }
}

__global__ void finalize_bn(int stage, float cnt,
                            const float* __restrict__ g, const float* __restrict__ bt)
{
    int j = threadIdx.x;
    float s1 = g_stats[stage * 256 + j];
    float s2 = g_stats[stage * 256 + 128 + j];
    float mu = s1 / cnt;
    float var = s2 / cnt - mu * mu;
    float a = g[j] * rsqrtf(var + EPS);
    g_bnA[stage * 128 + j] = a;
    g_bnC[stage * 128 + j] = bt[j] - mu * a;
}

__global__ void __launch_bounds__(256)
scatter_kernel(const int* __restrict__ dst, int nedges)
{
    int lane = threadIdx.x & 31;
    int warp = (blockIdx.x * 256 + threadIdx.x) >> 5;
    int nw = (gridDim.x * 256) >> 5;
    float4 A0 = reinterpret_cast<const float4*>(g_bnA)[lane];
    float4 C0 = reinterpret_cast<const float4*>(g_bnC)[lane];
    float4 A1 = reinterpret_cast<const float4*>(g_bnA + 128)[lane];
    float4 C1 = reinterpret_cast<const float4*>(g_bnC + 128)[lane];
    for (int e = warp; e < nedges; e += nw) {
        int d = __ldg(dst + e);
        float4 t = reinterpret_cast<const float4*>(g_t1 + (size_t)e * D)[lane];
        float4 u = reinterpret_cast<const float4*>(g_u + (size_t)e * D)[lane];
        float4 h;
        h.x = (t.x * A0.x + C0.x) + (u.x * A1.x + C1.x);
        h.y = (t.y * A0.y + C0.y) + (u.y * A1.y + C1.y);
        h.z = (t.z * A0.z + C0.z) + (u.z * A1.z + C1.z);
        h.w = (t.w * A0.w + C0.w) + (u.w * A1.w + C1.w);
        float* base = g_agg + (size_t)d * D + lane * 4;
        asm volatile("red.global.add.v4.f32 [%0], {%1, %2, %3, %4};"
                     :: "l"(base), "f"(h.x), "f"(h.y), "f"(h.z), "f"(h.w)
                     : "memory");
        if (lane == 0) atomicAdd(&g_deg[d], 1.f);
    }
}

__global__ void __launch_bounds__(256, 1)
node_final_kernel(const float* __restrict__ eW1, int nrows)
{
    extern __shared__ float smemf[];
    float* Hs = smemf;
    float* Ws = smemf + 128 * PADX;
    const int tid = threadIdx.x;
    const int tx = tid & 15, ty = tid >> 4;
    const int row0 = blockIdx.x * 128;

#pragma unroll
    for (int t = 0; t < 16; t++) {
        int idx = tid + t * 256;
        int r = idx >> 5;
        int c4 = (idx & 31) << 2;
        int gr = row0 + r;
        float4 h = make_float4(0.f, 0.f, 0.f, 0.f);
        if (gr < nrows) {
            float4 v = *reinterpret_cast<const float4*>(g_v + (size_t)gr * D + c4);
            float4 w = *reinterpret_cast<const float4*>(g_w + (size_t)gr * D + c4);
            float4 A2 = reinterpret_cast<const float4*>(g_bnA + 256)[c4 >> 2];
            float4 C2 = reinterpret_cast<const float4*>(g_bnC + 256)[c4 >> 2];
            float4 A3 = reinterpret_cast<const float4*>(g_bnA + 384)[c4 >> 2];
            float4 C3 = reinterpret_cast<const float4*>(g_bnC + 384)[c4 >> 2];
            h.x = (w.x * A3.x + C3.x) + (v.x * A2.x + C2.x);
            h.y = (w.y * A3.y + C3.y) + (v.y * A2.y + C2.y);
            h.z = (w.z * A3.z + C3.z) + (v.z * A2.z + C2.z);
            h.w = (w.w * A3.w + C3.w) + (v.w * A2.w + C2.w);
        }
        *reinterpret_cast<float4*>(Hs + r * PADX + c4) = h;
        reinterpret_cast<float4*>(Ws)[idx] =
            reinterpret_cast<const float4*>(eW1 + 128 * 128)[idx];
    }
    __syncthreads();

    float2 acc[8][4];
#pragma unroll
    for (int j = 0; j < 8; j++)
#pragma unroll
        for (int p = 0; p < 4; p++) acc[j][p] = make_float2(0.f, 0.f);
    gemm_tile(Hs, Ws, acc, tx, ty);
    __syncthreads();

#pragma unroll
    for (int j = 0; j < 8; j++) {
        int gr = row0 + ty + 16 * j;
        if (gr < nrows)
#pragma unroll
            for (int p = 0; p < 4; p++) {
                g_P1[(size_t)gr * D + tx + 32 * p]      = acc[j][p].x;
                g_P1[(size_t)gr * D + tx + 32 * p + 16] = acc[j][p].y;
            }
    }
#pragma unroll
    for (int t = 0; t < 16; t++) {
        int idx = tid + t * 256;
        reinterpret_cast<float4*>(Ws)[idx] =
            reinterpret_cast<const float4*>(eW1 + 256 * 128)[idx];
    }
    __syncthreads();

#pragma unroll
    for (int j = 0; j < 8; j++)
#pragma unroll
        for (int p = 0; p < 4; p++) acc[j][p] = make_float2(0.f, 0.f);
    gemm_tile(Hs, Ws, acc, tx, ty);

#pragma unroll
    for (int j = 0; j < 8; j++) {
        int gr = row0 + ty + 16 * j;
        if (gr < nrows)
#pragma unroll
            for (int p = 0; p < 4; p++) {
                g_P2[(size_t)gr * D + tx + 32 * p]      = acc[j][p].x;
                g_P2[(size_t)gr * D + tx + 32 * p + 16] = acc[j][p].y;
            }
    }
}

__global__ void norm_out_kernel(float* __restrict__ out, int n4)
{
    int idx = blockIdx.x * blockDim.x + threadIdx.x;
    if (idx >= n4) return;
    int cv = idx & 31;
    float4 A = reinterpret_cast<const float4*>(g_bnA + 512)[cv];
    float4 C = reinterpret_cast<const float4*>(g_bnC + 512)[cv];
    float4 v = reinterpret_cast<float4*>(out)[idx];
    v.x = v.x * A.x + C.x;
    v.y = v.y * A.y + C.y;
    v.z = v.z * A.z + C.z;
    v.w = v.w * A.w + C.w;
    reinterpret_cast<float4*>(out)[idx] = v;
}

// ---------------- host orchestration ----------------
extern "C" void kernel_launch(void* const* d_in, const int* in_sizes, int n_in,
                              void* d_out, int out_size)
{
    if (n_in < 15) return;
    const float* edata = (const float*)d_in[0];
    const int*   src   = (const int*)d_in[1];
    const int*   dst   = (const int*)d_in[2];
    int w = (n_in >= 16) ? 4 : 3;
    const float* W1s = (const float*)d_in[w + 0];
    const float* b1s = (const float*)d_in[w + 1];
    const float* W2s = (const float*)d_in[w + 2];
    const float* b2s = (const float*)d_in[w + 3];
    const float* gs  = (const float*)d_in[w + 4];
    const float* bts = (const float*)d_in[w + 5];
    const float* eW1 = (const float*)d_in[w + 6];
    const float* eb1 = (const float*)d_in[w + 7];
    const float* eW2 = (const float*)d_in[w + 8];
    const float* eb2 = (const float*)d_in[w + 9];
    const float* eg  = (const float*)d_in[w + 10];
    const float* ebt = (const float*)d_in[w + 11];

    int E = in_sizes[0] / D;
    int N = 20000;

    float *p_t1, *p_u, *p_v, *p_w2, *p_agg, *p_deg, *p_stats, *p_bnA, *p_bnC;
    cudaGetSymbolAddress((void**)&p_t1, g_t1);
    cudaGetSymbolAddress((void**)&p_u, g_u);
    cudaGetSymbolAddress((void**)&p_v, g_v);
    cudaGetSymbolAddress((void**)&p_w2, g_w);
    cudaGetSymbolAddress((void**)&p_agg, g_agg);
    cudaGetSymbolAddress((void**)&p_deg, g_deg);
    cudaGetSymbolAddress((void**)&p_stats, g_stats);
    cudaGetSymbolAddress((void**)&p_bnA, g_bnA);
    cudaGetSymbolAddress((void**)&p_bnC, g_bnC);

    cudaFuncSetAttribute(mlp_kernel, cudaFuncAttributeMaxDynamicSharedMemorySize, SMEM_BYTES);
    cudaFuncSetAttribute(node_final_kernel, cudaFuncAttributeMaxDynamicSharedMemorySize, SMEM_BYTES);
    cudaFuncSetAttribute(tc_mlp_tpl<false>, cudaFuncAttributeMaxDynamicSharedMemorySize, TC_SMEM);
    cudaFuncSetAttribute(tc_mlp_tpl<true>,  cudaFuncAttributeMaxDynamicSharedMemorySize, TC_SMEM);

    cudaMemsetAsync(p_stats, 0, 5 * 2 * 128 * sizeof(float), 0);
    cudaMemsetAsync(p_agg, 0, (size_t)NODE_CAP * D * sizeof(float), 0);
    cudaMemsetAsync(p_deg, 0, NODE_CAP * sizeof(float), 0);

    int egrid = (E + 127) / 128;
    int ngrid = (N + 127) / 128;

    // weight prep: transpose + bf16 hi/lo split
    prep_weights<<<(6 * 16384 + 255) / 256, 256>>>(W1s, W2s, eW1, eW2);

    // edge MLP0 (tensor cores)
    tc_mlp_tpl<false><<<egrid, 256, TC_SMEM>>>(edata, 0, 1, b1s, b2s,
                                               p_t1, E, 0, 0, nullptr, nullptr,
                                               nullptr, nullptr);
    finalize_bn<<<1, 128>>>(0, (float)E, gs, bts);
    // edge MLP1 (input = BN0(t1), folded affine)
    tc_mlp_tpl<false><<<egrid, 256, TC_SMEM>>>(p_t1, 2, 3, b1s + 128, b2s + 128,
                                               p_u, E, 1, 1, p_bnA, p_bnC,
                                               nullptr, nullptr);
    finalize_bn<<<1, 128>>>(1, (float)E, gs + 128, bts + 128);
    // h_e = BN0(t1)+BN1(u); scatter-sum + degree
    scatter_kernel<<<2048, 256>>>(dst, E);
    // node MLP2 (input = agg / max(deg,1)) — SIMT
    mlp_kernel<<<ngrid, 256, SMEM_BYTES>>>(p_agg, W1s + 2 * 16384, b1s + 256,
                                           W2s + 2 * 16384, b2s + 256,
                                           p_v, N, 2, 2, nullptr, nullptr, p_deg);
    finalize_bn<<<1, 128>>>(2, (float)N, gs + 256, bts + 256);
    // node MLP3 — SIMT
    mlp_kernel<<<ngrid, 256, SMEM_BYTES>>>(p_v, W1s + 3 * 16384, b1s + 384,
                                           W2s + 3 * 16384, b2s + 384,
                                           p_w2, N, 1, 3, p_bnA + 256, p_bnC + 256, nullptr);
    finalize_bn<<<1, 128>>>(3, (float)N, gs + 384, bts + 384);
    // h_n + per-node partials P1/P2 through eW1 src/dst slices — SIMT
    node_final_kernel<<<ngrid, 256, SMEM_BYTES>>>(eW1, N);
    // final edge MLP (tensor cores, with gathers) -> d_out (pre-BN)
    tc_mlp_tpl<true><<<egrid, 256, TC_SMEM>>>(edata, 4, 5, eb1, eb2,
                                              (float*)d_out, E, 0, 4, nullptr, nullptr,
                                              src, dst);
    finalize_bn<<<1, 128>>>(4, (float)E, eg, ebt);
    int n4 = E * (D / 4);
    norm_out_kernel<<<(n4 + 255) / 256, 256>>>((float*)d_out, n4);
}

// round 7
// speedup vs baseline: 2.2663x; 1.1600x over previous
#include <cuda_runtime.h>
#include <cuda_bf16.h>
#include <math.h>
#include <stdint.h>

#define D 128
#define EPS 1e-5f
#define PADX 132
#define NODE_CAP 20096
#define E_MAX 640000

static const int SMEM_BYTES = (128 * PADX + 128 * 128) * 4;  // SIMT kernels
// TC kernel smem: 6 tiles (Ah, Al, W1h, W1l, W2h, W2l), 128 rows x 272 bytes
#define TILE_PITCH 272
#define TILE_BYTES_PAD (128 * TILE_PITCH)  // 34816
static const int TC_SMEM = 6 * TILE_BYTES_PAD;  // 208896

// ---------------- scratch ----------------
__device__ float g_t1[(size_t)E_MAX * D];
__device__ float g_u [(size_t)E_MAX * D];
__device__ float g_v [(size_t)NODE_CAP * D];
__device__ float g_w [(size_t)NODE_CAP * D];
__device__ float g_P1[(size_t)NODE_CAP * D];
__device__ float g_P2[(size_t)NODE_CAP * D];
__device__ float g_agg[(size_t)NODE_CAP * D];
__device__ float g_deg[NODE_CAP];
__device__ float g_stats[5 * 2 * 128];
__device__ float g_bnA[5 * 128];
__device__ float g_bnC[5 * 128];
// prepped weights: 6 matrices x (hi,lo), each [n][k] bf16 128x128 = 32KB
__device__ __align__(256) unsigned char g_wprep[12 * 32768];

// ---------------- helpers ----------------
// fast ELU: exp(x)-1 via ex2.approx (abs err ~2^-22, fine for 1e-3 budget)
__device__ __forceinline__ float elu1(float x) {
    float e;
    asm("ex2.approx.f32 %0, %1;" : "=f"(e) : "f"(x * 1.4426950408889634f));
    return x > 0.f ? x : (e - 1.0f);
}

__device__ __forceinline__ uint32_t smem_u32(const void* p) {
    uint32_t a;
    asm("{ .reg .u64 t; cvta.to.shared.u64 t, %1; cvt.u32.u64 %0, t; }" : "=r"(a) : "l"(p));
    return a;
}

#define CP_ASYNC16(dst, src) \
    asm volatile("cp.async.cg.shared.global [%0], [%1], 16;" :: "r"(dst), "l"(src))
#define CP_COMMIT() asm volatile("cp.async.commit_group;")
#define CP_WAIT1()  asm volatile("cp.async.wait_group 1;")
#define CP_WAIT0()  asm volatile("cp.async.wait_group 0;")

// truncation split: hi = a with low 16 bits zeroed (exact bf16), lo = bf16(a - hi)
__device__ __forceinline__ void split2t(float a, float b, uint32_t& hi, uint32_t& lo) {
    uint32_t ai = __float_as_uint(a), bi = __float_as_uint(b);
    hi = __byte_perm(ai, bi, 0x7632);  // {a.hi16 in low, b.hi16 in high}
    float la = a - __uint_as_float(ai & 0xFFFF0000u);
    float lb = b - __uint_as_float(bi & 0xFFFF0000u);
    asm("cvt.rn.bf16x2.f32 %0, %1, %2;" : "=r"(lo) : "f"(lb), "f"(la));
}

// split 8 fp32 -> bf16 hi/lo, 16B stores to padded tiles
__device__ __forceinline__ void split_store8(const float* v, unsigned char* Ah,
                                             unsigned char* Al, uint32_t off) {
    uint32_t hw[4], lw[4];
#pragma unroll
    for (int i = 0; i < 4; i++) split2t(v[2 * i], v[2 * i + 1], hw[i], lw[i]);
    *reinterpret_cast<uint4*>(Ah + off) = make_uint4(hw[0], hw[1], hw[2], hw[3]);
    *reinterpret_cast<uint4*>(Al + off) = make_uint4(lw[0], lw[1], lw[2], lw[3]);
}

__device__ __forceinline__ void ldm4(uint32_t* r, uint32_t a) {
    asm volatile("ldmatrix.sync.aligned.m8n8.x4.shared.b16 {%0,%1,%2,%3}, [%4];"
                 : "=r"(r[0]), "=r"(r[1]), "=r"(r[2]), "=r"(r[3]) : "r"(a));
}

__device__ __forceinline__ void mma16816(float* c, const uint32_t* a, const uint32_t* b) {
    asm volatile(
        "mma.sync.aligned.m16n8k16.row.col.f32.bf16.bf16.f32 "
        "{%0,%1,%2,%3}, {%4,%5,%6,%7}, {%8,%9}, {%0,%1,%2,%3};"
        : "+f"(c[0]), "+f"(c[1]), "+f"(c[2]), "+f"(c[3])
        : "r"(a[0]), "r"(a[1]), "r"(a[2]), "r"(a[3]), "r"(b[0]), "r"(b[1]));
}

// fused 3-split warp GEMM, k-outer, warp tile m32 x n32 (16 warps cover 128x128)
__device__ __forceinline__ void warp_gemm3(uint32_t Ah, uint32_t Al,
                                           uint32_t Wh, uint32_t Wl,
                                           int lane, int wm, int wn,
                                           float acc[2][4][4]) {
    const int arow = lane & 15;
    const int kA = ((lane >> 4) << 3) * 2;               // byte k-offset
    const int brow = ((lane >> 4) << 3) + (lane & 7);
    const int kB = (((lane >> 3) & 1) << 3) * 2;
    const uint32_t aoff0 = (uint32_t)((wm * 32 + arow) * TILE_PITCH) + kA;
    const uint32_t aoff1 = aoff0 + 16 * TILE_PITCH;
    uint32_t boff[2];
#pragma unroll
    for (int p = 0; p < 2; p++)
        boff[p] = (uint32_t)((wn * 32 + p * 16 + brow) * TILE_PITCH) + kB;

#pragma unroll
    for (int k0 = 0; k0 < 128; k0 += 16) {
        uint32_t ah0[4], ah1[4], al0[4], al1[4], bh[2][4], bl[2][4];
        ldm4(ah0, Ah + aoff0 + k0 * 2);
        ldm4(ah1, Ah + aoff1 + k0 * 2);
        ldm4(al0, Al + aoff0 + k0 * 2);
        ldm4(al1, Al + aoff1 + k0 * 2);
#pragma unroll
        for (int p = 0; p < 2; p++) ldm4(bh[p], Wh + boff[p] + k0 * 2);
#pragma unroll
        for (int p = 0; p < 2; p++) ldm4(bl[p], Wl + boff[p] + k0 * 2);
#pragma unroll
        for (int j = 0; j < 4; j++) {
            const uint32_t* bhj = &bh[j >> 1][(j & 1) * 2];
            mma16816(acc[0][j], ah0, bhj);
            mma16816(acc[1][j], ah1, bhj);
        }
#pragma unroll
        for (int j = 0; j < 4; j++) {
            const uint32_t* bhj = &bh[j >> 1][(j & 1) * 2];
            mma16816(acc[0][j], al0, bhj);
            mma16816(acc[1][j], al1, bhj);
        }
#pragma unroll
        for (int j = 0; j < 4; j++) {
            const uint32_t* blj = &bl[j >> 1][(j & 1) * 2];
            mma16816(acc[0][j], ah0, blj);
            mma16816(acc[1][j], ah1, blj);
        }
    }
}

// ---------------- weight prep: transpose + bf16 split ----------------
// m: 0:W1s[0] 1:W2s[0] 2:W1s[1] 3:W2s[1] 4:eW1[0:128,:] 5:eW2
__global__ void prep_weights(const float* __restrict__ W1s, const float* __restrict__ W2s,
                             const float* __restrict__ eW1, const float* __restrict__ eW2)
{
    int idx = blockIdx.x * 256 + threadIdx.x;
    if (idx >= 6 * 16384) return;
    int m = idx >> 14;
    int e = idx & 16383;
    int n = e >> 7, k = e & 127;
    const float* W;
    switch (m) {
        case 0: W = W1s; break;
        case 1: W = W2s; break;
        case 2: W = W1s + 16384; break;
        case 3: W = W2s + 16384; break;
        case 4: W = eW1; break;
        default: W = eW2; break;
    }
    float v = W[k * 128 + n];
    __nv_bfloat16 h = __float2bfloat16(v);
    __nv_bfloat16 l = __float2bfloat16(v - __bfloat162float(h));
    *reinterpret_cast<__nv_bfloat16*>(g_wprep + (size_t)(2 * m) * 32768 + (size_t)e * 2) = h;
    *reinterpret_cast<__nv_bfloat16*>(g_wprep + (size_t)(2 * m + 1) * 32768 + (size_t)e * 2) = l;
}

// ---------------- tensor-core fused MLP over 128-row tiles, 512 threads ----
template <bool GATHER>
__global__ void __launch_bounds__(512, 1)
tc_mlp_tpl(const float* __restrict__ X, int m1, int m2,
           const float* __restrict__ B1, const float* __restrict__ B2,
           float* __restrict__ out, int nrows, int mode, int stage,
           const float* __restrict__ preA, const float* __restrict__ preC,
           const int* __restrict__ srcI, const int* __restrict__ dstI)
{
    extern __shared__ unsigned char smem[];
    unsigned char* Ah  = smem;
    unsigned char* Al  = smem + TILE_BYTES_PAD;
    unsigned char* W1h = smem + 2 * TILE_BYTES_PAD;
    unsigned char* W1l = smem + 3 * TILE_BYTES_PAD;
    unsigned char* W2h = smem + 4 * TILE_BYTES_PAD;
    unsigned char* W2l = smem + 5 * TILE_BYTES_PAD;
    __shared__ float sB1[128], sB2[128], sPA[128], sPC[128];
    __shared__ int sSrc[128], sDst[128];

    const int tid = threadIdx.x, wid = tid >> 5, lane = tid & 31;
    const int wm = wid & 3, wn = wid >> 2;       // warp tile: rows 32*wm, cols 32*wn
    const int g = lane >> 2, tig = lane & 3;
    const int row0 = blockIdx.x * 128;

    // ---- async W1 prefetch (group old), W2 prefetch (group young) ----
    {
        const char* g1 = (const char*)(g_wprep + (size_t)(2 * m1) * 32768);
        const char* g2 = (const char*)(g_wprep + (size_t)(2 * m2) * 32768);
#pragma unroll
        for (int t = 0; t < 4; t++) {
            int idx = tid + 512 * t;
            uint32_t off = (uint32_t)((idx >> 4) * TILE_PITCH + (idx & 15) * 16);
            CP_ASYNC16(smem_u32(W1h + off), g1 + (size_t)idx * 16);
            CP_ASYNC16(smem_u32(W1l + off), g1 + 32768 + (size_t)idx * 16);
        }
        CP_COMMIT();
#pragma unroll
        for (int t = 0; t < 4; t++) {
            int idx = tid + 512 * t;
            uint32_t off = (uint32_t)((idx >> 4) * TILE_PITCH + (idx & 15) * 16);
            CP_ASYNC16(smem_u32(W2h + off), g2 + (size_t)idx * 16);
            CP_ASYNC16(smem_u32(W2l + off), g2 + 32768 + (size_t)idx * 16);
        }
        CP_COMMIT();
    }

    if (tid < 128) {
        sB1[tid] = B1[tid];
        sB2[tid] = B2[tid];
        if (mode == 1) { sPA[tid] = preA[tid]; sPC[tid] = preC[tid]; }
        if (GATHER) {
            int gr = row0 + tid;
            sSrc[tid] = (gr < nrows) ? srcI[gr] : 0;
            sDst[tid] = (gr < nrows) ? dstI[gr] : 0;
        }
    }
    __syncthreads();  // sPA/sPC visible before A-load uses them

    // ---- coalesced load + split A tile (8-float groups, lane-contiguous) ----
#pragma unroll
    for (int t = 0; t < 4; t++) {
        int q = tid + 512 * t;        // 2048 groups of 8 floats
        int r = q >> 4;
        int kp = (q & 15) << 3;
        int gr = row0 + r;
        float v[8];
        if (gr < nrows) {
            float4 a = *reinterpret_cast<const float4*>(X + (size_t)gr * D + kp);
            float4 b = *reinterpret_cast<const float4*>(X + (size_t)gr * D + kp + 4);
            v[0] = a.x; v[1] = a.y; v[2] = a.z; v[3] = a.w;
            v[4] = b.x; v[5] = b.y; v[6] = b.z; v[7] = b.w;
            if (mode == 1) {
#pragma unroll
                for (int i = 0; i < 8; i++) v[i] = v[i] * sPA[kp + i] + sPC[kp + i];
            }
        } else {
#pragma unroll
            for (int i = 0; i < 8; i++) v[i] = 0.f;
        }
        split_store8(v, Ah, Al, (uint32_t)(r * TILE_PITCH + kp * 2));
    }
    CP_WAIT1();       // W1 resident
    __syncthreads();

    const uint32_t uAh = smem_u32(Ah), uAl = smem_u32(Al);

    // ---- GEMM1 ----
    float acc[2][4][4];
#pragma unroll
    for (int i = 0; i < 2; i++)
#pragma unroll
        for (int j = 0; j < 4; j++) {
            int col = wn * 32 + j * 8 + 2 * tig;
            acc[i][j][0] = sB1[col]; acc[i][j][1] = sB1[col + 1];
            acc[i][j][2] = sB1[col]; acc[i][j][3] = sB1[col + 1];
        }
    warp_gemm3(uAh, uAl, smem_u32(W1h), smem_u32(W1l), lane, wm, wn, acc);
    __syncthreads();  // all warps done reading Ah/Al before rewrite

    // ---- epilogue1: h1 = elu(acc [+ P1[src]+P2[dst]]); re-split into A ----
#pragma unroll
    for (int i = 0; i < 2; i++) {
        int r0 = wm * 32 + i * 16 + g;
        int r1 = r0 + 8;
#pragma unroll
        for (int j = 0; j < 4; j++) {
            int col = wn * 32 + j * 8 + 2 * tig;
            float v0 = acc[i][j][0], v1 = acc[i][j][1];
            float v2 = acc[i][j][2], v3 = acc[i][j][3];
            if (GATHER) {
                const float2 p1a = *reinterpret_cast<const float2*>(g_P1 + (size_t)sSrc[r0] * D + col);
                const float2 p2a = *reinterpret_cast<const float2*>(g_P2 + (size_t)sDst[r0] * D + col);
                const float2 p1b = *reinterpret_cast<const float2*>(g_P1 + (size_t)sSrc[r1] * D + col);
                const float2 p2b = *reinterpret_cast<const float2*>(g_P2 + (size_t)sDst[r1] * D + col);
                v0 += p1a.x + p2a.x; v1 += p1a.y + p2a.y;
                v2 += p1b.x + p2b.x; v3 += p1b.y + p2b.y;
            }
            v0 = elu1(v0); v1 = elu1(v1); v2 = elu1(v2); v3 = elu1(v3);
            uint32_t hi, lo;
            split2t(v0, v1, hi, lo);
            *reinterpret_cast<uint32_t*>(Ah + r0 * TILE_PITCH + col * 2) = hi;
            *reinterpret_cast<uint32_t*>(Al + r0 * TILE_PITCH + col * 2) = lo;
            split2t(v2, v3, hi, lo);
            *reinterpret_cast<uint32_t*>(Ah + r1 * TILE_PITCH + col * 2) = hi;
            *reinterpret_cast<uint32_t*>(Al + r1 * TILE_PITCH + col * 2) = lo;
        }
    }
    CP_WAIT0();       // W2 resident
    __syncthreads();

    // ---- GEMM2 ----
#pragma unroll
    for (int i = 0; i < 2; i++)
#pragma unroll
        for (int j = 0; j < 4; j++) {
            int col = wn * 32 + j * 8 + 2 * tig;
            acc[i][j][0] = sB2[col]; acc[i][j][1] = sB2[col + 1];
            acc[i][j][2] = sB2[col]; acc[i][j][3] = sB2[col + 1];
        }
    warp_gemm3(uAh, uAl, smem_u32(W2h), smem_u32(W2l), lane, wm, wn, acc);

    // ---- epilogue2: h2 = elu(acc) -> gmem + smem scratch (stats) ----
    // scratch overlays W1h/W1l (GEMM2 reads only W2h/W2l/A tiles -> safe)
    float* scratch = reinterpret_cast<float*>(W1h);  // 128 x 132 fp32 = 67584 B
#pragma unroll
    for (int i = 0; i < 2; i++) {
        int r0 = wm * 32 + i * 16 + g;
        int r1 = r0 + 8;
        int gr0 = row0 + r0, gr1 = row0 + r1;
        bool va = gr0 < nrows, vb = gr1 < nrows;
#pragma unroll
        for (int j = 0; j < 4; j++) {
            int col = wn * 32 + j * 8 + 2 * tig;
            float v0 = va ? elu1(acc[i][j][0]) : 0.f;
            float v1 = va ? elu1(acc[i][j][1]) : 0.f;
            float v2 = vb ? elu1(acc[i][j][2]) : 0.f;
            float v3 = vb ? elu1(acc[i][j][3]) : 0.f;
            *reinterpret_cast<float2*>(scratch + r0 * 132 + col) = make_float2(v0, v1);
            *reinterpret_cast<float2*>(scratch + r1 * 132 + col) = make_float2(v2, v3);
            if (va) *reinterpret_cast<float2*>(out + (size_t)gr0 * D + col) = make_float2(v0, v1);
            if (vb) *reinterpret_cast<float2*>(out + (size_t)gr1 * D + col) = make_float2(v2, v3);
        }
    }
    __syncthreads();

    // 512 threads: col = tid&127, row-block (tid>>7)*32
    {
        int col = tid & 127;
        int rb = (tid >> 7) * 32;
        float s = 0.f, q = 0.f;
#pragma unroll 4
        for (int r = rb; r < rb + 32; r++) {
            float vv = scratch[r * 132 + col];
            s += vv; q += vv * vv;
        }
        atomicAdd(&g_stats[stage * 256 + col], s);
        atomicAdd(&g_stats[stage * 256 + 128 + col], q);
    }
}

// ---------------- SIMT path for small node stages ----------------
__device__ __forceinline__ float2 ffma2(float2 d, float2 a, float2 b) {
    asm("fma.rn.f32x2 %0, %1, %2, %0;"
        : "+l"(reinterpret_cast<unsigned long long&>(d))
        : "l"(reinterpret_cast<unsigned long long&>(a)),
          "l"(reinterpret_cast<unsigned long long&>(b)));
    return d;
}

__device__ __forceinline__ void gemm_tile(const float* __restrict__ Xs,
                                          const float* __restrict__ Ws,
                                          float2 acc[8][4], int tx, int ty) {
#pragma unroll 2
    for (int k = 0; k < 128; k++) {
        float xv[8];
        float2 ww[4];
#pragma unroll
        for (int j = 0; j < 8; j++) xv[j] = Xs[(ty + 16 * j) * PADX + k];
#pragma unroll
        for (int p = 0; p < 4; p++) {
            float w0 = Ws[k * 128 + tx + 32 * p];
            float w1 = Ws[k * 128 + tx + 32 * p + 16];
            ww[p] = make_float2(w0, w1);
        }
#pragma unroll
        for (int j = 0; j < 8; j++) {
            float2 xx = make_float2(xv[j], xv[j]);
#pragma unroll
            for (int p = 0; p < 4; p++) acc[j][p] = ffma2(acc[j][p], xx, ww[p]);
        }
    }
}

__global__ void __launch_bounds__(256, 1)
mlp_kernel(const float* __restrict__ X,
           const float* __restrict__ W1, const float* __restrict__ B1,
           const float* __restrict__ W2, const float* __restrict__ B2,
           float* __restrict__ out, int nrows, int mode, int stage,
           const float* __restrict__ preA, const float* __restrict__ preC,
           const float* __restrict__ degp)
{
    extern __shared__ float smemf[];
    float* Xs = smemf;
    float* Ws = smemf + 128 * PADX;
    __shared__ float sB[128];
    __shared__ float sPA[128], sPC[128], sDeg[128];

    const int tid = threadIdx.x;
    const int tx = tid & 15, ty = tid >> 4;
    const int row0 = blockIdx.x * 128;

    if (tid < 128) {
        sB[tid] = B1[tid];
        if (mode == 1) { sPA[tid] = preA[tid]; sPC[tid] = preC[tid]; }
        if (mode == 2) {
            int r = row0 + tid;
            sDeg[tid] = (r < nrows) ? (1.f / fmaxf(degp[r], 1.f)) : 0.f;
        }
    }
    __syncthreads();

#pragma unroll
    for (int t = 0; t < 16; t++) {
        int idx = tid + t * 256;
        int r = idx >> 5;
        int c4 = (idx & 31) << 2;
        int gr = row0 + r;
        float4 v = make_float4(0.f, 0.f, 0.f, 0.f);
        if (gr < nrows) {
            v = *reinterpret_cast<const float4*>(X + (size_t)gr * D + c4);
            if (mode == 1) {
                v.x = v.x * sPA[c4] + sPC[c4];
                v.y = v.y * sPA[c4 + 1] + sPC[c4 + 1];
                v.z = v.z * sPA[c4 + 2] + sPC[c4 + 2];
                v.w = v.w * sPA[c4 + 3] + sPC[c4 + 3];
            } else if (mode == 2) {
                float s = sDeg[r];
                v.x *= s; v.y *= s; v.z *= s; v.w *= s;
            }
        }
        *reinterpret_cast<float4*>(Xs + r * PADX + c4) = v;
        reinterpret_cast<float4*>(Ws)[idx] = reinterpret_cast<const float4*>(W1)[idx];
    }
    __syncthreads();

    float2 acc[8][4];
#pragma unroll
    for (int j = 0; j < 8; j++)
#pragma unroll
        for (int p = 0; p < 4; p++)
            acc[j][p] = make_float2(sB[tx + 32 * p], sB[tx + 32 * p + 16]);

    gemm_tile(Xs, Ws, acc, tx, ty);
#pragma unroll
    for (int j = 0; j < 8; j++)
#pragma unroll
        for (int p = 0; p < 4; p++) {
            acc[j][p].x = elu1(acc[j][p].x);
            acc[j][p].y = elu1(acc[j][p].y);
        }
    __syncthreads();

#pragma unroll
    for (int j = 0; j < 8; j++) {
        int r = ty + 16 * j;
#pragma unroll
        for (int p = 0; p < 4; p++) {
            Xs[r * PADX + tx + 32 * p]      = acc[j][p].x;
            Xs[r * PADX + tx + 32 * p + 16] = acc[j][p].y;
        }
    }
#pragma unroll
    for (int t = 0; t < 16; t++) {
        int idx = tid + t * 256;
        reinterpret_cast<float4*>(Ws)[idx] = reinterpret_cast<const float4*>(W2)[idx];
    }
    if (tid < 128) sB[tid] = B2[tid];
    __syncthreads();

#pragma unroll
    for (int j = 0; j < 8; j++)
#pragma unroll
        for (int p = 0; p < 4; p++)
            acc[j][p] = make_float2(sB[tx + 32 * p], sB[tx + 32 * p + 16]);

    gemm_tile(Xs, Ws, acc, tx, ty);
#pragma unroll
    for (int j = 0; j < 8; j++)
#pragma unroll
        for (int p = 0; p < 4; p++) {
            acc[j][p].x = elu1(acc[j][p].x);
            acc[j][p].y = elu1(acc[j][p].y);
        }
    __syncthreads();

#pragma unroll
    for (int j = 0; j < 8; j++) {
        int r = ty + 16 * j;
        int gr = row0 + r;
        bool valid = gr < nrows;
#pragma unroll
        for (int p = 0; p < 4; p++) {
            int c0 = tx + 32 * p, c1 = c0 + 16;
            float vx = valid ? acc[j][p].x : 0.f;
            float vy = valid ? acc[j][p].y : 0.f;
            Xs[r * PADX + c0] = vx;
            Xs[r * PADX + c1] = vy;
            if (valid) {
                out[(size_t)gr * D + c0] = vx;
                out[(size_t)gr * D + c1] = vy;
            }
        }
    }
    __syncthreads();

    if (tid < 128) {
        float s = 0.f, q = 0.f;
#pragma unroll 4
        for (int r = 0; r < 128; r++) {
            float vv = Xs[r * PADX + tid];
            s += vv; q += vv * vv;
        }
        atomicAdd(&g_stats[stage * 256 + tid], s);
        atomicAdd(&g_stats[stage * 256 + 128 + tid], q);
    }
}

__global__ void finalize_bn(int stage, float cnt,
                            const float* __restrict__ g, const float* __restrict__ bt)
{
    int j = threadIdx.x;
    float s1 = g_stats[stage * 256 + j];
    float s2 = g_stats[stage * 256 + 128 + j];
    float mu = s1 / cnt;
    float var = s2 / cnt - mu * mu;
    float a = g[j] * rsqrtf(var + EPS);
    g_bnA[stage * 128 + j] = a;
    g_bnC[stage * 128 + j] = bt[j] - mu * a;
}

__global__ void __launch_bounds__(256)
scatter_kernel(const int* __restrict__ dst, int nedges)
{
    int lane = threadIdx.x & 31;
    int warp = (blockIdx.x * 256 + threadIdx.x) >> 5;
    int nw = (gridDim.x * 256) >> 5;
    float4 A0 = reinterpret_cast<const float4*>(g_bnA)[lane];
    float4 C0 = reinterpret_cast<const float4*>(g_bnC)[lane];
    float4 A1 = reinterpret_cast<const float4*>(g_bnA + 128)[lane];
    float4 C1 = reinterpret_cast<const float4*>(g_bnC + 128)[lane];
    for (int e = warp; e < nedges; e += nw) {
        int d = __ldg(dst + e);
        float4 t = reinterpret_cast<const float4*>(g_t1 + (size_t)e * D)[lane];
        float4 u = reinterpret_cast<const float4*>(g_u + (size_t)e * D)[lane];
        float4 h;
        h.x = (t.x * A0.x + C0.x) + (u.x * A1.x + C1.x);
        h.y = (t.y * A0.y + C0.y) + (u.y * A1.y + C1.y);
        h.z = (t.z * A0.z + C0.z) + (u.z * A1.z + C1.z);
        h.w = (t.w * A0.w + C0.w) + (u.w * A1.w + C1.w);
        float* base = g_agg + (size_t)d * D + lane * 4;
        asm volatile("red.global.add.v4.f32 [%0], {%1, %2, %3, %4};"
                     :: "l"(base), "f"(h.x), "f"(h.y), "f"(h.z), "f"(h.w)
                     : "memory");
        if (lane == 0) atomicAdd(&g_deg[d], 1.f);
    }
}

__global__ void __launch_bounds__(256, 1)
node_final_kernel(const float* __restrict__ eW1, int nrows)
{
    extern __shared__ float smemf[];
    float* Hs = smemf;
    float* Ws = smemf + 128 * PADX;
    const int tid = threadIdx.x;
    const int tx = tid & 15, ty = tid >> 4;
    const int row0 = blockIdx.x * 128;

#pragma unroll
    for (int t = 0; t < 16; t++) {
        int idx = tid + t * 256;
        int r = idx >> 5;
        int c4 = (idx & 31) << 2;
        int gr = row0 + r;
        float4 h = make_float4(0.f, 0.f, 0.f, 0.f);
        if (gr < nrows) {
            float4 v = *reinterpret_cast<const float4*>(g_v + (size_t)gr * D + c4);
            float4 w = *reinterpret_cast<const float4*>(g_w + (size_t)gr * D + c4);
            float4 A2 = reinterpret_cast<const float4*>(g_bnA + 256)[c4 >> 2];
            float4 C2 = reinterpret_cast<const float4*>(g_bnC + 256)[c4 >> 2];
            float4 A3 = reinterpret_cast<const float4*>(g_bnA + 384)[c4 >> 2];
            float4 C3 = reinterpret_cast<const float4*>(g_bnC + 384)[c4 >> 2];
            h.x = (w.x * A3.x + C3.x) + (v.x * A2.x + C2.x);
            h.y = (w.y * A3.y + C3.y) + (v.y * A2.y + C2.y);
            h.z = (w.z * A3.z + C3.z) + (v.z * A2.z + C2.z);
            h.w = (w.w * A3.w + C3.w) + (v.w * A2.w + C2.w);
        }
        *reinterpret_cast<float4*>(Hs + r * PADX + c4) = h;
        reinterpret_cast<float4*>(Ws)[idx] =
            reinterpret_cast<const float4*>(eW1 + 128 * 128)[idx];
    }
    __syncthreads();

    float2 acc[8][4];
#pragma unroll
    for (int j = 0; j < 8; j++)
#pragma unroll
        for (int p = 0; p < 4; p++) acc[j][p] = make_float2(0.f, 0.f);
    gemm_tile(Hs, Ws, acc, tx, ty);
    __syncthreads();

#pragma unroll
    for (int j = 0; j < 8; j++) {
        int gr = row0 + ty + 16 * j;
        if (gr < nrows)
#pragma unroll
            for (int p = 0; p < 4; p++) {
                g_P1[(size_t)gr * D + tx + 32 * p]      = acc[j][p].x;
                g_P1[(size_t)gr * D + tx + 32 * p + 16] = acc[j][p].y;
            }
    }
#pragma unroll
    for (int t = 0; t < 16; t++) {
        int idx = tid + t * 256;
        reinterpret_cast<float4*>(Ws)[idx] =
            reinterpret_cast<const float4*>(eW1 + 256 * 128)[idx];
    }
    __syncthreads();

#pragma unroll
    for (int j = 0; j < 8; j++)
#pragma unroll
        for (int p = 0; p < 4; p++) acc[j][p] = make_float2(0.f, 0.f);
    gemm_tile(Hs, Ws, acc, tx, ty);

#pragma unroll
    for (int j = 0; j < 8; j++) {
        int gr = row0 + ty + 16 * j;
        if (gr < nrows)
#pragma unroll
            for (int p = 0; p < 4; p++) {
                g_P2[(size_t)gr * D + tx + 32 * p]      = acc[j][p].x;
                g_P2[(size_t)gr * D + tx + 32 * p + 16] = acc[j][p].y;
            }
    }
}

__global__ void norm_out_kernel(float* __restrict__ out, int n4)
{
    int idx = blockIdx.x * blockDim.x + threadIdx.x;
    if (idx >= n4) return;
    int cv = idx & 31;
    float4 A = reinterpret_cast<const float4*>(g_bnA + 512)[cv];
    float4 C = reinterpret_cast<const float4*>(g_bnC + 512)[cv];
    float4 v = reinterpret_cast<float4*>(out)[idx];
    v.x = v.x * A.x + C.x;
    v.y = v.y * A.y + C.y;
    v.z = v.z * A.z + C.z;
    v.w = v.w * A.w + C.w;
    reinterpret_cast<float4*>(out)[idx] = v;
}

// ---------------- host orchestration ----------------
extern "C" void kernel_launch(void* const* d_in, const int* in_sizes, int n_in,
                              void* d_out, int out_size)
{
    if (n_in < 15) return;
    const float* edata = (const float*)d_in[0];
    const int*   src   = (const int*)d_in[1];
    const int*   dst   = (const int*)d_in[2];
    int w = (n_in >= 16) ? 4 : 3;
    const float* W1s = (const float*)d_in[w + 0];
    const float* b1s = (const float*)d_in[w + 1];
    const float* W2s = (const float*)d_in[w + 2];
    const float* b2s = (const float*)d_in[w + 3];
    const float* gs  = (const float*)d_in[w + 4];
    const float* bts = (const float*)d_in[w + 5];
    const float* eW1 = (const float*)d_in[w + 6];
    const float* eb1 = (const float*)d_in[w + 7];
    const float* eW2 = (const float*)d_in[w + 8];
    const float* eb2 = (const float*)d_in[w + 9];
    const float* eg  = (const float*)d_in[w + 10];
    const float* ebt = (const float*)d_in[w + 11];

    int E = in_sizes[0] / D;
    int N = 20000;

    float *p_t1, *p_u, *p_v, *p_w2, *p_agg, *p_deg, *p_stats, *p_bnA, *p_bnC;
    cudaGetSymbolAddress((void**)&p_t1, g_t1);
    cudaGetSymbolAddress((void**)&p_u, g_u);
    cudaGetSymbolAddress((void**)&p_v, g_v);
    cudaGetSymbolAddress((void**)&p_w2, g_w);
    cudaGetSymbolAddress((void**)&p_agg, g_agg);
    cudaGetSymbolAddress((void**)&p_deg, g_deg);
    cudaGetSymbolAddress((void**)&p_stats, g_stats);
    cudaGetSymbolAddress((void**)&p_bnA, g_bnA);
    cudaGetSymbolAddress((void**)&p_bnC, g_bnC);

    cudaFuncSetAttribute(mlp_kernel, cudaFuncAttributeMaxDynamicSharedMemorySize, SMEM_BYTES);
    cudaFuncSetAttribute(node_final_kernel, cudaFuncAttributeMaxDynamicSharedMemorySize, SMEM_BYTES);
    cudaFuncSetAttribute(tc_mlp_tpl<false>, cudaFuncAttributeMaxDynamicSharedMemorySize, TC_SMEM);
    cudaFuncSetAttribute(tc_mlp_tpl<true>,  cudaFuncAttributeMaxDynamicSharedMemorySize, TC_SMEM);

    cudaMemsetAsync(p_stats, 0, 5 * 2 * 128 * sizeof(float), 0);
    cudaMemsetAsync(p_agg, 0, (size_t)NODE_CAP * D * sizeof(float), 0);
    cudaMemsetAsync(p_deg, 0, NODE_CAP * sizeof(float), 0);

    int egrid = (E + 127) / 128;
    int ngrid = (N + 127) / 128;

    // weight prep: transpose + bf16 hi/lo split
    prep_weights<<<(6 * 16384 + 255) / 256, 256>>>(W1s, W2s, eW1, eW2);

    // edge MLP0 (tensor cores)
    tc_mlp_tpl<false><<<egrid, 512, TC_SMEM>>>(edata, 0, 1, b1s, b2s,
                                               p_t1, E, 0, 0, nullptr, nullptr,
                                               nullptr, nullptr);
    finalize_bn<<<1, 128>>>(0, (float)E, gs, bts);
    // edge MLP1 (input = BN0(t1), folded affine)
    tc_mlp_tpl<false><<<egrid, 512, TC_SMEM>>>(p_t1, 2, 3, b1s + 128, b2s + 128,
                                               p_u, E, 1, 1, p_bnA, p_bnC,
                                               nullptr, nullptr);
    finalize_bn<<<1, 128>>>(1, (float)E, gs + 128, bts + 128);
    // h_e = BN0(t1)+BN1(u); scatter-sum + degree
    scatter_kernel<<<2048, 256>>>(dst, E);
    // node MLP2 (input = agg / max(deg,1)) — SIMT
    mlp_kernel<<<ngrid, 256, SMEM_BYTES>>>(p_agg, W1s + 2 * 16384, b1s + 256,
                                           W2s + 2 * 16384, b2s + 256,
                                           p_v, N, 2, 2, nullptr, nullptr, p_deg);
    finalize_bn<<<1, 128>>>(2, (float)N, gs + 256, bts + 256);
    // node MLP3 — SIMT
    mlp_kernel<<<ngrid, 256, SMEM_BYTES>>>(p_v, W1s + 3 * 16384, b1s + 384,
                                           W2s + 3 * 16384, b2s + 384,
                                           p_w2, N, 1, 3, p_bnA + 256, p_bnC + 256, nullptr);
    finalize_bn<<<1, 128>>>(3, (float)N, gs + 384, bts + 384);
    // h_n + per-node partials P1/P2 through eW1 src/dst slices — SIMT
    node_final_kernel<<<ngrid, 256, SMEM_BYTES>>>(eW1, N);
    // final edge MLP (tensor cores, with gathers) -> d_out (pre-BN)
    tc_mlp_tpl<true><<<egrid, 512, TC_SMEM>>>(edata, 4, 5, eb1, eb2,
                                              (float*)d_out, E, 0, 4, nullptr, nullptr,
                                              src, dst);
    finalize_bn<<<1, 128>>>(4, (float)E, eg, ebt);
    int n4 = E * (D / 4);
    norm_out_kernel<<<(n4 + 255) / 256, 256>>>((float*)d_out, n4);
}